// round 2
// baseline (speedup 1.0000x reference)
#include <cuda_runtime.h>
#include <cstdint>

#define N_NODES 50000
#define N_EDGES 800000
#define NF 64
#define NH 128
#define NOUT 64
#define NMU 100
#define IN_DIM (2*NF + NMU)   /* 228 */

#define TROWS 2049            /* RBF lookup table rows, r in [0,10], h = 10/2048 */
#define TBL_INVH 204.8f       /* 2048/10 */

#define ETILE 64
#define ETHREADS 512
#define HPAD 132              /* padded hdn row (floats) */

#define NODE_TILE 64
#define NODE_THREADS 256

// ---------------- device scratch (no allocations allowed) ----------------
__device__ float g_P1[N_NODES * NH];   // h @ W1[:, :64].T   per node
__device__ float g_P2[N_NODES * NH];   // h @ W1[:, 64:128].T per node
__device__ float g_T [TROWS * NH];     // RBF-contribution lookup table
__device__ int   g_src[N_EDGES];
__device__ int   g_dst[N_EDGES];
__device__ int   g_is64;

// ---------------- index dtype detection + conversion ----------------
__global__ void detect_kernel(const unsigned int* __restrict__ w) {
    // If src is int64 (values < 50000 >= 0), every odd 32-bit word is 0.
    // If src is int32, odd words are actual node indices (overwhelmingly nonzero).
    int is64 = 1;
    for (int i = 0; i < 256; ++i) {
        if (w[2 * i + 1] != 0u) { is64 = 0; break; }
    }
    g_is64 = is64;
}

__global__ void convert_kernel(const void* __restrict__ s, const void* __restrict__ d) {
    int i = blockIdx.x * blockDim.x + threadIdx.x;
    if (i >= N_EDGES) return;
    if (g_is64) {
        g_src[i] = (int)((const long long*)s)[i];
        g_dst[i] = (int)((const long long*)d)[i];
    } else {
        g_src[i] = ((const int*)s)[i];
        g_dst[i] = ((const int*)d)[i];
    }
}

// ---------------- RBF lookup table build ----------------
// T[i][j] = sum_k exp(-10 * (mu[k] - r_i)^2) * W1[j][128 + k],  r_i = i * (10/2048)
__global__ void table_kernel(const float* __restrict__ mu, const float* __restrict__ W1) {
    int i = blockIdx.x;
    int j = threadIdx.x;
    float r = (float)i * (10.0f / 2048.0f);
    float acc = 0.0f;
#pragma unroll 4
    for (int k = 0; k < NMU; ++k) {
        float dmu = mu[k] - r;
        acc += expf(-10.0f * dmu * dmu) * W1[j * IN_DIM + 2 * NF + k];
    }
    g_T[i * NH + j] = acc;
}

// ---------------- per-node partial GEMM: P1 / P2 ----------------
// P1[n][j] = sum_f h[n][f] * W1[j][f]       (f in 0..63)
// P2[n][j] = sum_f h[n][f] * W1[j][64+f]
__global__ void __launch_bounds__(NODE_THREADS, 2)
node_kernel(const float* __restrict__ h, const float* __restrict__ W1) {
    extern __shared__ float sm[];
    float* hS  = sm;                       // [64][64]
    float* W1S = sm + NODE_TILE * NF;      // [128][128]  W1S[f*128+j] = W1[j][f]

    int tid = threadIdx.x;
    int nb = blockIdx.x * NODE_TILE;
    int nCnt = N_NODES - nb; if (nCnt > NODE_TILE) nCnt = NODE_TILE;

    for (int idx = tid; idx < 128 * 128; idx += NODE_THREADS) {
        int f = idx >> 7, j = idx & 127;
        W1S[idx] = W1[j * IN_DIM + f];
    }
    for (int idx = tid; idx < NODE_TILE * NF; idx += NODE_THREADS) {
        hS[idx] = (idx < nCnt * NF) ? h[nb * NF + idx] : 0.0f;
    }
    __syncthreads();

    int j = tid & 127;
    int which = tid >> 7;                  // 0 -> P1, 1 -> P2
    const float* wbase = W1S + which * 64 * 128 + j;
    float* outP = which ? g_P2 : g_P1;

    for (int n0 = 0; n0 < NODE_TILE; n0 += 8) {
        float acc[8];
#pragma unroll
        for (int ni = 0; ni < 8; ++ni) acc[ni] = 0.0f;
#pragma unroll
        for (int f = 0; f < 64; f += 4) {
            float w0 = wbase[(f + 0) * 128];
            float w1 = wbase[(f + 1) * 128];
            float w2 = wbase[(f + 2) * 128];
            float w3 = wbase[(f + 3) * 128];
#pragma unroll
            for (int ni = 0; ni < 8; ++ni) {
                float4 hv = *(const float4*)&hS[(n0 + ni) * NF + f];
                acc[ni] += hv.x * w0 + hv.y * w1 + hv.z * w2 + hv.w * w3;
            }
        }
#pragma unroll
        for (int ni = 0; ni < 8; ++ni) {
            int n = n0 + ni;
            if (n < nCnt) outP[(nb + n) * NH + j] = acc[ni];
        }
    }
}

// ---------------- fused edge kernel ----------------
// pre[j]  = P1[src][j] + P2[dst][j] + lerp(T, r)[j]
// hdn[j]  = silu(pre[j])
// out[o]  = sum_j hdn[j] * W2[o][j]
__global__ void __launch_bounds__(ETHREADS, 2)
edge_kernel(const float* __restrict__ enorm, const float* __restrict__ W2,
            float* __restrict__ out) {
    extern __shared__ float sm[];
    float* W2TS = sm;                              // [128][64]  W2TS[j*64+o] = W2[o][j]
    float* hdnS = sm + NH * NOUT;                  // [64][HPAD]
    float* rS   = hdnS + ETILE * HPAD;             // [64]
    int*   sS   = (int*)(rS + ETILE);              // [64]
    int*   dS   = sS + ETILE;                      // [64]

    int tid = threadIdx.x;

    for (int idx = tid; idx < NH * NOUT; idx += ETHREADS) {
        int j = idx >> 6, o = idx & 63;
        W2TS[idx] = W2[o * NH + j];
    }

    int ntiles = N_EDGES / ETILE;
    for (int tile = blockIdx.x; tile < ntiles; tile += gridDim.x) {
        int eb = tile * ETILE;
        __syncthreads();   // covers W2TS fill (1st iter) and hdnS reuse (later iters)

        if (tid < ETILE) {
            sS[tid] = g_src[eb + tid];
            dS[tid] = g_dst[eb + tid];
            rS[tid] = enorm[eb + tid];
        }
        __syncthreads();

        // ---- phase 1: gather + table lerp + SiLU -> hdnS ----
        {
            int e  = tid >> 3;               // 64 edges, 8 threads each
            int j0 = (tid & 7) * 16;         // 16 j's per thread
            int s = sS[e], d = dS[e];
            float r = rS[e];
            float u = r * TBL_INVH;
            int i0 = (int)u;
            if (i0 > 2047) i0 = 2047;
            if (i0 < 0)    i0 = 0;
            float fr = u - (float)i0;
            const float4* p1p = (const float4*)&g_P1[s * NH + j0];
            const float4* p2p = (const float4*)&g_P2[d * NH + j0];
            const float4* t0p = (const float4*)&g_T[i0 * NH + j0];
            const float4* t1p = (const float4*)&g_T[(i0 + 1) * NH + j0];
#pragma unroll
            for (int gI = 0; gI < 4; ++gI) {
                float4 a  = __ldcg(p1p + gI);     // L2-resident, keep out of L1
                float4 b  = __ldcg(p2p + gI);
                float4 c  = t0p[gI];              // table: small, let L1 cache it
                float4 dd = t1p[gI];
                float4 pre;
                pre.x = a.x + b.x + c.x + fr * (dd.x - c.x);
                pre.y = a.y + b.y + c.y + fr * (dd.y - c.y);
                pre.z = a.z + b.z + c.z + fr * (dd.z - c.z);
                pre.w = a.w + b.w + c.w + fr * (dd.w - c.w);
                float4 hv;
                hv.x = pre.x / (1.0f + __expf(-pre.x));
                hv.y = pre.y / (1.0f + __expf(-pre.y));
                hv.z = pre.z / (1.0f + __expf(-pre.z));
                hv.w = pre.w / (1.0f + __expf(-pre.w));
                *(float4*)&hdnS[e * HPAD + j0 + gI * 4] = hv;
            }
        }
        __syncthreads();

        // ---- phase 2: out[e][o] = sum_j hdn[e][j] * W2[o][j] ----
        {
            int o0 = (tid & 15) * 4;         // 4 outputs
            int e0 = (tid >> 4) * 2;         // 2 edges
            float4 acc0 = make_float4(0.f, 0.f, 0.f, 0.f);
            float4 acc1 = make_float4(0.f, 0.f, 0.f, 0.f);
            const float* h0 = &hdnS[e0 * HPAD];
            const float* h1 = &hdnS[(e0 + 1) * HPAD];
#pragma unroll 4
            for (int j = 0; j < NH; j += 4) {
                float4 ha = *(const float4*)&h0[j];
                float4 hb = *(const float4*)&h1[j];
                float4 w0 = *(const float4*)&W2TS[(j + 0) * NOUT + o0];
                float4 w1 = *(const float4*)&W2TS[(j + 1) * NOUT + o0];
                float4 w2 = *(const float4*)&W2TS[(j + 2) * NOUT + o0];
                float4 w3 = *(const float4*)&W2TS[(j + 3) * NOUT + o0];
                acc0.x += ha.x * w0.x + ha.y * w1.x + ha.z * w2.x + ha.w * w3.x;
                acc0.y += ha.x * w0.y + ha.y * w1.y + ha.z * w2.y + ha.w * w3.y;
                acc0.z += ha.x * w0.z + ha.y * w1.z + ha.z * w2.z + ha.w * w3.z;
                acc0.w += ha.x * w0.w + ha.y * w1.w + ha.z * w2.w + ha.w * w3.w;
                acc1.x += hb.x * w0.x + hb.y * w1.x + hb.z * w2.x + hb.w * w3.x;
                acc1.y += hb.x * w0.y + hb.y * w1.y + hb.z * w2.y + hb.w * w3.y;
                acc1.z += hb.x * w0.z + hb.y * w1.z + hb.z * w2.z + hb.w * w3.z;
                acc1.w += hb.x * w0.w + hb.y * w1.w + hb.z * w2.w + hb.w * w3.w;
            }
            __stcs((float4*)&out[(size_t)(eb + e0) * NOUT + o0], acc0);
            __stcs((float4*)&out[(size_t)(eb + e0 + 1) * NOUT + o0], acc1);
        }
    }
}

// ---------------- launcher ----------------
extern "C" void kernel_launch(void* const* d_in, const int* in_sizes, int n_in,
                              void* d_out, int out_size) {
    const float* h   = (const float*)d_in[0];
    const void*  src = d_in[1];
    const void*  dst = d_in[2];
    const float* en  = (const float*)d_in[3];
    const float* mu  = (const float*)d_in[4];
    const float* W1  = (const float*)d_in[5];
    const float* W2  = (const float*)d_in[6];
    float* out = (float*)d_out;

    const int NODE_SMEM = (NODE_TILE * NF + 128 * 128) * 4;                 // 81920 B
    const int EDGE_SMEM = (NH * NOUT + ETILE * HPAD + ETILE) * 4            // W2TS+hdnS+rS
                          + ETILE * 2 * 4;                                  // sS+dS
    cudaFuncSetAttribute(node_kernel, cudaFuncAttributeMaxDynamicSharedMemorySize, NODE_SMEM);
    cudaFuncSetAttribute(edge_kernel, cudaFuncAttributeMaxDynamicSharedMemorySize, EDGE_SMEM);

    detect_kernel<<<1, 1>>>((const unsigned int*)src);
    convert_kernel<<<(N_EDGES + 255) / 256, 256>>>(src, dst);
    table_kernel<<<TROWS, NH>>>(mu, W1);
    node_kernel<<<(N_NODES + NODE_TILE - 1) / NODE_TILE, NODE_THREADS, NODE_SMEM>>>(h, W1);
    edge_kernel<<<296, ETHREADS, EDGE_SMEM>>>(en, W2, out);
}

// round 7
// speedup vs baseline: 1.3232x; 1.3232x over previous
#include <cuda_runtime.h>
#include <cuda_bf16.h>
#include <cstdint>

#define N_NODES 50000
#define N_EDGES 800000
#define NF 64
#define NH 128
#define NOUT 64
#define NMU 100
#define IN_DIM (2*NF + NMU)   /* 228 */

#define TROWS 2049            /* RBF lookup table rows, r in [0,10], h = 10/2048 */
#define TBL_INVH 204.8f       /* 2048/10 */

#define NODE_TILE 64
#define NODE_THREADS 256

#define ETILE 128             /* edges per tile */
#define ETHREADS 256
#define NTILES (N_EDGES / ETILE)   /* 6250 exactly */

#define APAD 136              /* padded hdn row, bf16 elems (136*2=272B, 68 words -> bank shift 4/row) */
#define ROWB (APAD * 2)       /* 272 bytes */

/* smem layout (bytes) */
#define SM_HDN_HI 0
#define SM_HDN_LO (128 * ROWB)            /* 34816 */
#define SM_IDX    (2 * 128 * ROWB)        /* 69632 */
#define EDGE_SMEM (SM_IDX + 128 * 12)     /* + sS,dS,rS = 71168 */

// ---------------- device scratch (no allocations allowed) ----------------
__device__ float g_P1[N_NODES * NH];   // h @ W1[:, :64].T   per node
__device__ float g_P2[N_NODES * NH];   // h @ W1[:, 64:128].T per node
__device__ float g_T [TROWS * NH];     // RBF-contribution lookup table
__device__ int   g_src[N_EDGES];
__device__ int   g_dst[N_EDGES];
__device__ int   g_is64;

// pack two f32 -> bf16x2; low half = first arg
__device__ __forceinline__ unsigned packbf(float lo_elem, float hi_elem) {
    unsigned r;
    asm("cvt.rn.bf16x2.f32 %0, %1, %2;" : "=r"(r) : "f"(hi_elem), "f"(lo_elem));
    return r;
}

__device__ __forceinline__ void mma_bf16(float& d0, float& d1, float& d2, float& d3,
                                         uint32_t a0, uint32_t a1, uint32_t a2, uint32_t a3,
                                         uint32_t b0, uint32_t b1) {
    asm volatile("mma.sync.aligned.m16n8k16.row.col.f32.bf16.bf16.f32 "
                 "{%0,%1,%2,%3}, {%4,%5,%6,%7}, {%8,%9}, {%0,%1,%2,%3};"
                 : "+f"(d0), "+f"(d1), "+f"(d2), "+f"(d3)
                 : "r"(a0), "r"(a1), "r"(a2), "r"(a3), "r"(b0), "r"(b1));
}

// ---------------- index dtype detection + conversion ----------------
__global__ void detect_kernel(const unsigned int* __restrict__ w) {
    int is64 = 1;
    for (int i = 0; i < 256; ++i) {
        if (w[2 * i + 1] != 0u) { is64 = 0; break; }
    }
    g_is64 = is64;
}

__global__ void convert_kernel(const void* __restrict__ s, const void* __restrict__ d) {
    int i = blockIdx.x * blockDim.x + threadIdx.x;
    if (i >= N_EDGES) return;
    if (g_is64) {
        g_src[i] = (int)((const long long*)s)[i];
        g_dst[i] = (int)((const long long*)d)[i];
    } else {
        g_src[i] = ((const int*)s)[i];
        g_dst[i] = ((const int*)d)[i];
    }
}

// ---------------- RBF lookup table build ----------------
__global__ void table_kernel(const float* __restrict__ mu, const float* __restrict__ W1) {
    int i = blockIdx.x;
    int j = threadIdx.x;
    float r = (float)i * (10.0f / 2048.0f);
    float acc = 0.0f;
#pragma unroll 4
    for (int k = 0; k < NMU; ++k) {
        float dmu = mu[k] - r;
        acc += expf(-10.0f * dmu * dmu) * W1[j * IN_DIM + 2 * NF + k];
    }
    g_T[i * NH + j] = acc;
}

// ---------------- per-node partial GEMM: P1 / P2 ----------------
__global__ void __launch_bounds__(NODE_THREADS, 2)
node_kernel(const float* __restrict__ h, const float* __restrict__ W1) {
    extern __shared__ float sm[];
    float* hS  = sm;                       // [64][64]
    float* W1S = sm + NODE_TILE * NF;      // [128][128]  W1S[f*128+j] = W1[j][f]

    int tid = threadIdx.x;
    int nb = blockIdx.x * NODE_TILE;
    int nCnt = N_NODES - nb; if (nCnt > NODE_TILE) nCnt = NODE_TILE;

    for (int idx = tid; idx < 128 * 128; idx += NODE_THREADS) {
        int f = idx >> 7, j = idx & 127;
        W1S[idx] = W1[j * IN_DIM + f];
    }
    for (int idx = tid; idx < NODE_TILE * NF; idx += NODE_THREADS) {
        hS[idx] = (idx < nCnt * NF) ? h[nb * NF + idx] : 0.0f;
    }
    __syncthreads();

    int j = tid & 127;
    int which = tid >> 7;                  // 0 -> P1, 1 -> P2
    const float* wbase = W1S + which * 64 * 128 + j;
    float* outP = which ? g_P2 : g_P1;

    for (int n0 = 0; n0 < NODE_TILE; n0 += 8) {
        float acc[8];
#pragma unroll
        for (int ni = 0; ni < 8; ++ni) acc[ni] = 0.0f;
#pragma unroll
        for (int f = 0; f < 64; f += 4) {
            float w0 = wbase[(f + 0) * 128];
            float w1 = wbase[(f + 1) * 128];
            float w2 = wbase[(f + 2) * 128];
            float w3 = wbase[(f + 3) * 128];
#pragma unroll
            for (int ni = 0; ni < 8; ++ni) {
                float4 hv = *(const float4*)&hS[(n0 + ni) * NF + f];
                acc[ni] += hv.x * w0 + hv.y * w1 + hv.z * w2 + hv.w * w3;
            }
        }
#pragma unroll
        for (int ni = 0; ni < 8; ++ni) {
            int n = n0 + ni;
            if (n < nCnt) outP[(nb + n) * NH + j] = acc[ni];
        }
    }
}

// ---------------- fused edge kernel: gather + lerp + SiLU -> split bf16 -> HMMA ----------------
// Output GEMM runs "transposed": A = W2 (held in registers, split hi/lo bf16),
// B = hdn (smem, split hi/lo bf16), D[n][e] accumulated in fp32 fragments.
// 3 passes fused per k-chunk: Ahi*Bhi + Alo*Bhi + Ahi*Blo  (drop Alo*Blo ~ 2^-18).
__global__ void __launch_bounds__(ETHREADS, 2)
edge_kernel(const float* __restrict__ enorm, const float* __restrict__ W2,
            float* __restrict__ out) {
    extern __shared__ __align__(16) char smc[];
    int tid  = threadIdx.x;
    int wid  = tid >> 5;
    int lane = tid & 31;
    int mc   = wid & 3;        // n-chunk (16 of 64 output cols)
    int half = wid >> 2;       // edge half (0: edges 0-63, 1: 64-127)

    int*   sS = (int*)  (smc + SM_IDX);
    int*   dS = sS + 128;
    float* rS = (float*)(dS + 128);

    // ---- one-time: W2 A-fragments (hi/lo split), held in registers ----
    uint32_t Ahi[8][4], Alo[8][4];
    {
        int r0 = mc * 16 + (lane >> 2);
        int q2 = (lane & 3) * 2;
#pragma unroll
        for (int kc = 0; kc < 8; ++kc) {
#pragma unroll
            for (int p = 0; p < 4; ++p) {
                int r = r0 + ((p & 1) ? 8 : 0);
                int k = kc * 16 + q2 + ((p & 2) ? 8 : 0);
                float2 w = *(const float2*)&W2[r * NH + k];
                unsigned hi = packbf(w.x, w.y);
                float l0 = w.x - __uint_as_float(hi << 16);
                float l1 = w.y - __uint_as_float(hi & 0xFFFF0000u);
                Ahi[kc][p] = hi;
                Alo[kc][p] = packbf(l0, l1);
            }
        }
    }

    for (int tile = blockIdx.x; tile < NTILES; tile += gridDim.x) {
        int eb = tile * ETILE;

        if (tid < ETILE) {
            sS[tid] = g_src[eb + tid];
            dS[tid] = g_dst[eb + tid];
            rS[tid] = enorm[eb + tid];
        }
        __syncthreads();

        // ---- phase 1: gather + lerp + SiLU -> split bf16 rows in smem ----
        {
            int e  = tid >> 1;
            int jh = tid & 1;
            int j0 = jh << 6;
            int s = sS[e], d = dS[e];
            float r = rS[e];
            float u = r * TBL_INVH;
            int i0 = (int)u;
            if (i0 > 2047) i0 = 2047;
            if (i0 < 0)    i0 = 0;
            float fr = u - (float)i0;
            const float4* P1p = (const float4*)(g_P1 + s * NH + j0);
            const float4* P2p = (const float4*)(g_P2 + d * NH + j0);
            const float4* T0p = (const float4*)(g_T + i0 * NH + j0);
            const float4* T1p = T0p + (NH / 4);
            char* hiRow = smc + SM_HDN_HI + e * ROWB + j0 * 2;
            char* loRow = smc + SM_HDN_LO + e * ROWB + j0 * 2;
#pragma unroll 4
            for (int g = 0; g < 16; ++g) {
                float4 a  = __ldcg(P1p + g);
                float4 b  = __ldcg(P2p + g);
                float4 c  = T0p[g];
                float4 t1 = T1p[g];
                float px = a.x + b.x + c.x + fr * (t1.x - c.x);
                float py = a.y + b.y + c.y + fr * (t1.y - c.y);
                float pz = a.z + b.z + c.z + fr * (t1.z - c.z);
                float pw = a.w + b.w + c.w + fr * (t1.w - c.w);
                float v0 = __fdividef(px, 1.0f + __expf(-px));
                float v1 = __fdividef(py, 1.0f + __expf(-py));
                float v2 = __fdividef(pz, 1.0f + __expf(-pz));
                float v3 = __fdividef(pw, 1.0f + __expf(-pw));
                unsigned p01 = packbf(v0, v1);
                unsigned p23 = packbf(v2, v3);
                float l0 = v0 - __uint_as_float(p01 << 16);
                float l1 = v1 - __uint_as_float(p01 & 0xFFFF0000u);
                float l2 = v2 - __uint_as_float(p23 << 16);
                float l3 = v3 - __uint_as_float(p23 & 0xFFFF0000u);
                *(uint2*)(hiRow + g * 8) = make_uint2(p01, p23);
                *(uint2*)(loRow + g * 8) = make_uint2(packbf(l0, l1), packbf(l2, l3));
            }
        }
        __syncthreads();

        // ---- phase 2: HMMA. Each warp: 16 output cols x 64 edges ----
        {
            // B-frag base for this lane: edge row = half*64 + ec*8 + lane/4, k word = lane%4
            const char* bHi0 = smc + SM_HDN_HI + (half * 64 + (lane >> 2)) * ROWB + (lane & 3) * 4;
            const char* bLo0 = smc + SM_HDN_LO + (half * 64 + (lane >> 2)) * ROWB + (lane & 3) * 4;
            int nb = mc * 16 + (lane >> 2);
#pragma unroll
            for (int ec = 0; ec < 8; ++ec) {
                const char* bHi = bHi0 + ec * 8 * ROWB;
                const char* bLo = bLo0 + ec * 8 * ROWB;
                float d0 = 0.f, d1 = 0.f, d2 = 0.f, d3 = 0.f;
#pragma unroll
                for (int kc = 0; kc < 8; ++kc) {
                    uint32_t b0h = *(const uint32_t*)(bHi + kc * 32);
                    uint32_t b1h = *(const uint32_t*)(bHi + kc * 32 + 16);
                    mma_bf16(d0, d1, d2, d3, Ahi[kc][0], Ahi[kc][1], Ahi[kc][2], Ahi[kc][3], b0h, b1h);
                    mma_bf16(d0, d1, d2, d3, Alo[kc][0], Alo[kc][1], Alo[kc][2], Alo[kc][3], b0h, b1h);
                    uint32_t b0l = *(const uint32_t*)(bLo + kc * 32);
                    uint32_t b1l = *(const uint32_t*)(bLo + kc * 32 + 16);
                    mma_bf16(d0, d1, d2, d3, Ahi[kc][0], Ahi[kc][1], Ahi[kc][2], Ahi[kc][3], b0l, b1l);
                }
                int e0 = eb + half * 64 + ec * 8 + (lane & 3) * 2;
                __stcs(&out[(size_t)e0 * NOUT + nb], d0);
                __stcs(&out[(size_t)(e0 + 1) * NOUT + nb], d1);
                __stcs(&out[(size_t)e0 * NOUT + nb + 8], d2);
                __stcs(&out[(size_t)(e0 + 1) * NOUT + nb + 8], d3);
            }
        }
        __syncthreads();   // hdnS reused next tile
    }
}

// ---------------- launcher ----------------
extern "C" void kernel_launch(void* const* d_in, const int* in_sizes, int n_in,
                              void* d_out, int out_size) {
    const float* h   = (const float*)d_in[0];
    const void*  src = d_in[1];
    const void*  dst = d_in[2];
    const float* en  = (const float*)d_in[3];
    const float* mu  = (const float*)d_in[4];
    const float* W1  = (const float*)d_in[5];
    const float* W2  = (const float*)d_in[6];
    float* out = (float*)d_out;

    const int NODE_SMEM = (NODE_TILE * NF + 128 * 128) * 4;   // 81920 B
    cudaFuncSetAttribute(node_kernel, cudaFuncAttributeMaxDynamicSharedMemorySize, NODE_SMEM);
    cudaFuncSetAttribute(edge_kernel, cudaFuncAttributeMaxDynamicSharedMemorySize, EDGE_SMEM);

    detect_kernel<<<1, 1>>>((const unsigned int*)src);
    convert_kernel<<<(N_EDGES + 255) / 256, 256>>>(src, dst);
    table_kernel<<<TROWS, NH>>>(mu, W1);
    node_kernel<<<(N_NODES + NODE_TILE - 1) / NODE_TILE, NODE_THREADS, NODE_SMEM>>>(h, W1);
    edge_kernel<<<296, ETHREADS, EDGE_SMEM>>>(en, W2, out);
}

// round 8
// speedup vs baseline: 1.4409x; 1.0890x over previous
#include <cuda_runtime.h>
#include <cuda_bf16.h>
#include <cstdint>

#define N_NODES 50000
#define N_EDGES 800000
#define NF 64
#define NH 128
#define NOUT 64
#define NMU 100
#define IN_DIM (2*NF + NMU)   /* 228 */

#define TROWS 2049            /* RBF lookup table rows, r in [0,10], h = 10/2048 */
#define TBL_INVH 204.8f       /* 2048/10 */

#define ETILE 128             /* edges per tile */
#define ETHREADS 384          /* 8 producer warps + 4 consumer warps */
#define NPROD 256
#define NTILES (N_EDGES / ETILE)   /* 6250 exactly */

#define APAD 136              /* padded hdn row, bf16 elems (68 words -> bank shift 4/row) */
#define ROWB (APAD * 2)       /* 272 bytes */
#define BUFB (128 * ROWB)     /* one bf16 matrix: 34816 B */
#define BUF_STRIDE (2 * BUFB) /* hi+lo: 69632 B */
#define EDGE_SMEM (2 * BUF_STRIDE)  /* 139264 B */

// ---------------- device scratch (no allocations allowed) ----------------
__device__ float g_P1[N_NODES * NH];   // h @ W1[:, :64].T   per node
__device__ float g_P2[N_NODES * NH];   // h @ W1[:, 64:128].T per node
__device__ float g_T [TROWS * NH];     // RBF-contribution lookup table
__device__ int   g_src[N_EDGES];
__device__ int   g_dst[N_EDGES];
__device__ int   g_is64;

// pack two f32 -> bf16x2; low half = first arg
__device__ __forceinline__ unsigned packbf(float lo_elem, float hi_elem) {
    unsigned r;
    asm("cvt.rn.bf16x2.f32 %0, %1, %2;" : "=r"(r) : "f"(hi_elem), "f"(lo_elem));
    return r;
}

__device__ __forceinline__ void mma4(float* d, const uint32_t* a, uint32_t b0, uint32_t b1) {
    asm volatile("mma.sync.aligned.m16n8k16.row.col.f32.bf16.bf16.f32 "
                 "{%0,%1,%2,%3}, {%4,%5,%6,%7}, {%8,%9}, {%0,%1,%2,%3};"
                 : "+f"(d[0]), "+f"(d[1]), "+f"(d[2]), "+f"(d[3])
                 : "r"(a[0]), "r"(a[1]), "r"(a[2]), "r"(a[3]), "r"(b0), "r"(b1));
}

#define BAR_SYNC(id)   asm volatile("bar.sync %0, 384;"   :: "r"(id) : "memory")
#define BAR_ARRIVE(id) asm volatile("bar.arrive %0, 384;" :: "r"(id) : "memory")
/* barrier ids: FULL buffer b -> 1+b, EMPTY buffer b -> 3+b */

// ---------------- index dtype detection + conversion ----------------
__global__ void detect_kernel(const unsigned int* __restrict__ w) {
    int is64 = 1;
    for (int i = 0; i < 256; ++i) {
        if (w[2 * i + 1] != 0u) { is64 = 0; break; }
    }
    g_is64 = is64;
}

__global__ void convert_kernel(const void* __restrict__ s, const void* __restrict__ d) {
    int i = blockIdx.x * blockDim.x + threadIdx.x;
    if (i >= N_EDGES) return;
    if (g_is64) {
        g_src[i] = (int)((const long long*)s)[i];
        g_dst[i] = (int)((const long long*)d)[i];
    } else {
        g_src[i] = ((const int*)s)[i];
        g_dst[i] = ((const int*)d)[i];
    }
}

// ---------------- RBF lookup table build ----------------
__global__ void table_kernel(const float* __restrict__ mu, const float* __restrict__ W1) {
    int i = blockIdx.x;
    int j = threadIdx.x;
    float r = (float)i * (10.0f / 2048.0f);
    float acc = 0.0f;
#pragma unroll 4
    for (int k = 0; k < NMU; ++k) {
        float dmu = mu[k] - r;
        acc += expf(-10.0f * dmu * dmu) * W1[j * IN_DIM + 2 * NF + k];
    }
    g_T[i * NH + j] = acc;
}

// ---------------- per-node partial GEMM via HMMA (split bf16, 3-pass) ----------------
// Tile: 128 nodes x 128 j. Warp w owns 16 nodes. A = h rows (regs), B = W1^T frags (global/L1).
// GEMM 0 (P1): k = f 0..63 vs W1[:, 0:64]; GEMM 1 (P2): same A vs W1[:, 64:128].
__global__ void __launch_bounds__(256, 4)
node_kernel(const float* __restrict__ h, const float* __restrict__ W1) {
    int tid = threadIdx.x, wid = tid >> 5, lane = tid & 31;
    int m0 = blockIdx.x * 128 + wid * 16 + (lane >> 2);

    uint32_t Ahi[4][4], Alo[4][4];
#pragma unroll
    for (int kc = 0; kc < 4; ++kc) {
#pragma unroll
        for (int p = 0; p < 4; ++p) {
            int row = m0 + ((p & 1) ? 8 : 0);
            int k = kc * 16 + (lane & 3) * 2 + ((p & 2) ? 8 : 0);
            float2 v = (row < N_NODES) ? *(const float2*)&h[row * NF + k] : make_float2(0.f, 0.f);
            unsigned hi = packbf(v.x, v.y);
            float l0 = v.x - __uint_as_float(hi << 16);
            float l1 = v.y - __uint_as_float(hi & 0xFFFF0000u);
            Ahi[kc][p] = hi;
            Alo[kc][p] = packbf(l0, l1);
        }
    }
    bool ok0 = m0 < N_NODES;
    bool ok1 = (m0 + 8) < N_NODES;
    int jn = lane >> 2;            // B frag n-index offset
    int jc = (lane & 3) * 2;       // D col offset

#pragma unroll 1
    for (int nc = 0; nc < 16; ++nc) {
        const float* wrow0 = W1 + (nc * 8 + jn) * IN_DIM;
#pragma unroll
        for (int g = 0; g < 2; ++g) {
            const float* wrow = wrow0 + g * 64;
            uint32_t Bh[4][2], Bl[4][2];
#pragma unroll
            for (int kc = 0; kc < 4; ++kc) {
#pragma unroll
                for (int q = 0; q < 2; ++q) {
                    float2 w = *(const float2*)&wrow[kc * 16 + (lane & 3) * 2 + q * 8];
                    unsigned hi = packbf(w.x, w.y);
                    float l0 = w.x - __uint_as_float(hi << 16);
                    float l1 = w.y - __uint_as_float(hi & 0xFFFF0000u);
                    Bh[kc][q] = hi;
                    Bl[kc][q] = packbf(l0, l1);
                }
            }
            float hh[4] = {0,0,0,0}, lh[4] = {0,0,0,0}, hl[4] = {0,0,0,0};
#pragma unroll
            for (int kc = 0; kc < 4; ++kc) {
                mma4(hh, Ahi[kc], Bh[kc][0], Bh[kc][1]);
                mma4(lh, Alo[kc], Bh[kc][0], Bh[kc][1]);
                mma4(hl, Ahi[kc], Bl[kc][0], Bl[kc][1]);
            }
            float d0 = hh[0] + lh[0] + hl[0];
            float d1 = hh[1] + lh[1] + hl[1];
            float d2 = hh[2] + lh[2] + hl[2];
            float d3 = hh[3] + lh[3] + hl[3];
            float* P = g ? g_P2 : g_P1;
            int col = nc * 8 + jc;
            if (ok0) *(float2*)&P[(size_t)m0 * NH + col] = make_float2(d0, d1);
            if (ok1) *(float2*)&P[(size_t)(m0 + 8) * NH + col] = make_float2(d2, d3);
        }
    }
}

// ---------------- fused edge kernel: warp-specialized producer/consumer ----------------
// Producers (warps 0-7): gather P1[src]+P2[dst]+lerp(T) -> SiLU -> split bf16 -> smem buffer.
// Consumers (warps 8-11): A = W2 in regs (hi/lo), B = hdn frags from smem, 3-pass HMMA -> out.
__global__ void __launch_bounds__(ETHREADS, 1)
edge_kernel(const float* __restrict__ enorm, const float* __restrict__ W2,
            float* __restrict__ out) {
    extern __shared__ __align__(16) char smc[];
    int tid  = threadIdx.x;
    int wid  = tid >> 5;
    int lane = tid & 31;

    if (tid < NPROD) {
        // ======================= PRODUCER =======================
        int e  = tid >> 1;
        int jh = tid & 1;
        int j0 = jh << 6;
        int it = 0;
        for (int tile = blockIdx.x; tile < NTILES; tile += gridDim.x, ++it) {
            int b = it & 1;
            if (it >= 2) BAR_SYNC(3 + b);            // wait EMPTY(b)
            int eg = tile * ETILE + e;
            int s = g_src[eg];
            int d = g_dst[eg];
            float r = __ldg(&enorm[eg]);
            float u = r * TBL_INVH;
            int i0 = (int)u;
            if (i0 > 2047) i0 = 2047;
            if (i0 < 0)    i0 = 0;
            float fr = u - (float)i0;
            const float4* P1p = (const float4*)(g_P1 + s * NH + j0);
            const float4* P2p = (const float4*)(g_P2 + d * NH + j0);
            const float4* T0p = (const float4*)(g_T + i0 * NH + j0);
            const float4* T1p = T0p + (NH / 4);
            char* hiRow = smc + b * BUF_STRIDE + e * ROWB + j0 * 2;
            char* loRow = hiRow + BUFB;
#pragma unroll 4
            for (int g = 0; g < 16; ++g) {
                float4 a  = __ldcg(P1p + g);
                float4 bb = __ldcg(P2p + g);
                float4 c  = T0p[g];
                float4 t1 = T1p[g];
                float px = a.x + bb.x + c.x + fr * (t1.x - c.x);
                float py = a.y + bb.y + c.y + fr * (t1.y - c.y);
                float pz = a.z + bb.z + c.z + fr * (t1.z - c.z);
                float pw = a.w + bb.w + c.w + fr * (t1.w - c.w);
                float v0 = __fdividef(px, 1.0f + __expf(-px));
                float v1 = __fdividef(py, 1.0f + __expf(-py));
                float v2 = __fdividef(pz, 1.0f + __expf(-pz));
                float v3 = __fdividef(pw, 1.0f + __expf(-pw));
                unsigned p01 = packbf(v0, v1);
                unsigned p23 = packbf(v2, v3);
                float l0 = v0 - __uint_as_float(p01 << 16);
                float l1 = v1 - __uint_as_float(p01 & 0xFFFF0000u);
                float l2 = v2 - __uint_as_float(p23 << 16);
                float l3 = v3 - __uint_as_float(p23 & 0xFFFF0000u);
                *(uint2*)(hiRow + g * 8) = make_uint2(p01, p23);
                *(uint2*)(loRow + g * 8) = make_uint2(packbf(l0, l1), packbf(l2, l3));
            }
            __threadfence_block();
            BAR_ARRIVE(1 + b);                       // signal FULL(b)
        }
    } else {
        // ======================= CONSUMER =======================
        int mc = wid - 8;                            // 16 output cols
        uint32_t Ahi[8][4], Alo[8][4];
        {
            int r0 = mc * 16 + (lane >> 2);
            int q2 = (lane & 3) * 2;
#pragma unroll
            for (int kc = 0; kc < 8; ++kc) {
#pragma unroll
                for (int p = 0; p < 4; ++p) {
                    int r = r0 + ((p & 1) ? 8 : 0);
                    int k = kc * 16 + q2 + ((p & 2) ? 8 : 0);
                    float2 w = *(const float2*)&W2[r * NH + k];
                    unsigned hi = packbf(w.x, w.y);
                    float l0 = w.x - __uint_as_float(hi << 16);
                    float l1 = w.y - __uint_as_float(hi & 0xFFFF0000u);
                    Ahi[kc][p] = hi;
                    Alo[kc][p] = packbf(l0, l1);
                }
            }
        }
        int nb = mc * 16 + (lane >> 2);
        int it = 0;
        for (int tile = blockIdx.x; tile < NTILES; tile += gridDim.x, ++it) {
            int b = it & 1;
            BAR_SYNC(1 + b);                         // wait FULL(b)
            const char* base = smc + b * BUF_STRIDE;
            int eb = tile * ETILE;
#pragma unroll 1
            for (int ec = 0; ec < 16; ec += 2) {
                const char* r0h = base + (ec * 8 + (lane >> 2)) * ROWB + (lane & 3) * 4;
                const char* r1h = r0h + 8 * ROWB;
                const char* r0l = r0h + BUFB;
                const char* r1l = r1h + BUFB;
                float hh0[4] = {0,0,0,0}, lh0[4] = {0,0,0,0}, hl0[4] = {0,0,0,0};
                float hh1[4] = {0,0,0,0}, lh1[4] = {0,0,0,0}, hl1[4] = {0,0,0,0};
#pragma unroll
                for (int kc = 0; kc < 8; ++kc) {
                    uint32_t b0h0 = *(const uint32_t*)(r0h + kc * 32);
                    uint32_t b1h0 = *(const uint32_t*)(r0h + kc * 32 + 16);
                    uint32_t b0h1 = *(const uint32_t*)(r1h + kc * 32);
                    uint32_t b1h1 = *(const uint32_t*)(r1h + kc * 32 + 16);
                    mma4(hh0, Ahi[kc], b0h0, b1h0);
                    mma4(hh1, Ahi[kc], b0h1, b1h1);
                    mma4(lh0, Alo[kc], b0h0, b1h0);
                    mma4(lh1, Alo[kc], b0h1, b1h1);
                    uint32_t b0l0 = *(const uint32_t*)(r0l + kc * 32);
                    uint32_t b1l0 = *(const uint32_t*)(r0l + kc * 32 + 16);
                    uint32_t b0l1 = *(const uint32_t*)(r1l + kc * 32);
                    uint32_t b1l1 = *(const uint32_t*)(r1l + kc * 32 + 16);
                    mma4(hl0, Ahi[kc], b0l0, b1l0);
                    mma4(hl1, Ahi[kc], b0l1, b1l1);
                }
                int e0 = eb + ec * 8 + (lane & 3) * 2;
                float d0 = hh0[0] + lh0[0] + hl0[0];
                float d1 = hh0[1] + lh0[1] + hl0[1];
                float d2 = hh0[2] + lh0[2] + hl0[2];
                float d3 = hh0[3] + lh0[3] + hl0[3];
                __stcs(&out[(size_t)e0 * NOUT + nb], d0);
                __stcs(&out[(size_t)(e0 + 1) * NOUT + nb], d1);
                __stcs(&out[(size_t)e0 * NOUT + nb + 8], d2);
                __stcs(&out[(size_t)(e0 + 1) * NOUT + nb + 8], d3);
                int e1 = e0 + 8;
                d0 = hh1[0] + lh1[0] + hl1[0];
                d1 = hh1[1] + lh1[1] + hl1[1];
                d2 = hh1[2] + lh1[2] + hl1[2];
                d3 = hh1[3] + lh1[3] + hl1[3];
                __stcs(&out[(size_t)e1 * NOUT + nb], d0);
                __stcs(&out[(size_t)(e1 + 1) * NOUT + nb], d1);
                __stcs(&out[(size_t)e1 * NOUT + nb + 8], d2);
                __stcs(&out[(size_t)(e1 + 1) * NOUT + nb + 8], d3);
            }
            BAR_ARRIVE(3 + b);                       // signal EMPTY(b)
        }
    }
}

// ---------------- launcher ----------------
extern "C" void kernel_launch(void* const* d_in, const int* in_sizes, int n_in,
                              void* d_out, int out_size) {
    const float* h   = (const float*)d_in[0];
    const void*  src = d_in[1];
    const void*  dst = d_in[2];
    const float* en  = (const float*)d_in[3];
    const float* mu  = (const float*)d_in[4];
    const float* W1  = (const float*)d_in[5];
    const float* W2  = (const float*)d_in[6];
    float* out = (float*)d_out;

    cudaFuncSetAttribute(edge_kernel, cudaFuncAttributeMaxDynamicSharedMemorySize, EDGE_SMEM);

    detect_kernel<<<1, 1>>>((const unsigned int*)src);
    convert_kernel<<<(N_EDGES + 255) / 256, 256>>>(src, dst);
    table_kernel<<<TROWS, NH>>>(mu, W1);
    node_kernel<<<(N_NODES + 127) / 128, 256>>>(h, W1);
    edge_kernel<<<148, ETHREADS, EDGE_SMEM>>>(en, W2, out);
}

// round 9
// speedup vs baseline: 2.5105x; 1.7423x over previous
#include <cuda_runtime.h>
#include <cuda_bf16.h>
#include <cstdint>

#define N_NODES 50000
#define N_EDGES 800000
#define NF 64
#define NH 128
#define NOUT 64
#define NMU 100
#define IN_DIM (2*NF + NMU)   /* 228 */

#define TROWS 2049            /* RBF lookup table rows, r in [0,10], h = 10/2048 */
#define TBL_INVH 204.8f       /* 2048/10 */

#define ETILE 128             /* edges per tile */
#define ETHREADS 384          /* 8 producer warps + 4 consumer warps */
#define NPROD 256
#define NTILES (N_EDGES / ETILE)   /* 6250 exactly */

#define APAD 136              /* padded hdn row, bf16 elems (68 words -> bank shift 4/row) */
#define ROWB (APAD * 2)       /* 272 bytes */
#define BUFB (128 * ROWB)     /* one bf16 matrix: 34816 B */
#define BUF_STRIDE (2 * BUFB) /* hi+lo: 69632 B */
#define EDGE_SMEM (2 * BUF_STRIDE)  /* 139264 B */

#define TBLK 16               /* table rows per block */
#define TSMEM ((NMU * NH + 128) * 4)   /* 51712 B */

// ---------------- device scratch (no allocations allowed) ----------------
__device__ float g_P1[N_NODES * NH];   // h @ W1[:, :64].T   per node
__device__ float g_P2[N_NODES * NH];   // h @ W1[:, 64:128].T per node
__device__ float g_T [TROWS * NH];     // RBF-contribution lookup table
__device__ int   g_src[N_EDGES];
__device__ int   g_dst[N_EDGES];
__device__ int   g_is64;

// pack two f32 -> bf16x2; low half = first arg
__device__ __forceinline__ unsigned packbf(float lo_elem, float hi_elem) {
    unsigned r;
    asm("cvt.rn.bf16x2.f32 %0, %1, %2;" : "=r"(r) : "f"(hi_elem), "f"(lo_elem));
    return r;
}

__device__ __forceinline__ void mma4(float* d, const uint32_t* a, uint32_t b0, uint32_t b1) {
    asm volatile("mma.sync.aligned.m16n8k16.row.col.f32.bf16.bf16.f32 "
                 "{%0,%1,%2,%3}, {%4,%5,%6,%7}, {%8,%9}, {%0,%1,%2,%3};"
                 : "+f"(d[0]), "+f"(d[1]), "+f"(d[2]), "+f"(d[3])
                 : "r"(a[0]), "r"(a[1]), "r"(a[2]), "r"(a[3]), "r"(b0), "r"(b1));
}

#define BAR_SYNC(id)   asm volatile("bar.sync %0, 384;"   :: "r"(id) : "memory")
#define BAR_ARRIVE(id) asm volatile("bar.arrive %0, 384;" :: "r"(id) : "memory")
/* barrier ids: FULL buffer b -> 1+b, EMPTY buffer b -> 3+b */

// ---------------- index dtype detection + conversion ----------------
__global__ void detect_kernel(const unsigned int* __restrict__ w) {
    int is64 = 1;
    for (int i = 0; i < 256; ++i) {
        if (w[2 * i + 1] != 0u) { is64 = 0; break; }
    }
    g_is64 = is64;
}

__global__ void convert_kernel(const void* __restrict__ s, const void* __restrict__ d) {
    int i = blockIdx.x * blockDim.x + threadIdx.x;
    if (i >= N_EDGES) return;
    if (g_is64) {
        g_src[i] = (int)((const long long*)s)[i];
        g_dst[i] = (int)((const long long*)d)[i];
    } else {
        g_src[i] = ((const int*)s)[i];
        g_dst[i] = ((const int*)d)[i];
    }
}

// ---------------- RBF lookup table build (smem-transposed W1c) ----------------
// Ws[k][j] = W1[j][128+k]; each block computes TBLK rows of g_T.
__global__ void __launch_bounds__(256, 1)
table_kernel(const float* __restrict__ mu, const float* __restrict__ W1) {
    extern __shared__ float tsm[];
    float* Ws  = tsm;             // [100][128]
    float* muS = tsm + NMU * NH;  // [100]
    int tid = threadIdx.x;

    for (int idx = tid; idx < NMU * NH; idx += 256) {
        int k = idx >> 7, j = idx & 127;
        Ws[k * NH + j] = W1[j * IN_DIM + 2 * NF + k];
    }
    if (tid < NMU) muS[tid] = mu[tid];
    __syncthreads();

    int ibase = blockIdx.x * TBLK;
#pragma unroll
    for (int q = 0; q < (TBLK * NH) / 256; ++q) {
        int o = q * 256 + tid;
        int i = ibase + (o >> 7);
        int j = o & 127;
        if (i < TROWS) {
            float r = (float)i * (10.0f / 2048.0f);
            float acc = 0.0f;
#pragma unroll 4
            for (int k = 0; k < NMU; ++k) {
                float dm = muS[k] - r;
                acc += __expf(-10.0f * dm * dm) * Ws[k * NH + j];
            }
            g_T[i * NH + j] = acc;
        }
    }
}

// ---------------- per-node partial GEMM via HMMA (split bf16, 3-pass) ----------------
__global__ void __launch_bounds__(256, 4)
node_kernel(const float* __restrict__ h, const float* __restrict__ W1) {
    int tid = threadIdx.x, wid = tid >> 5, lane = tid & 31;
    int m0 = blockIdx.x * 128 + wid * 16 + (lane >> 2);

    uint32_t Ahi[4][4], Alo[4][4];
#pragma unroll
    for (int kc = 0; kc < 4; ++kc) {
#pragma unroll
        for (int p = 0; p < 4; ++p) {
            int row = m0 + ((p & 1) ? 8 : 0);
            int k = kc * 16 + (lane & 3) * 2 + ((p & 2) ? 8 : 0);
            float2 v = (row < N_NODES) ? *(const float2*)&h[row * NF + k] : make_float2(0.f, 0.f);
            unsigned hi = packbf(v.x, v.y);
            float l0 = v.x - __uint_as_float(hi << 16);
            float l1 = v.y - __uint_as_float(hi & 0xFFFF0000u);
            Ahi[kc][p] = hi;
            Alo[kc][p] = packbf(l0, l1);
        }
    }
    bool ok0 = m0 < N_NODES;
    bool ok1 = (m0 + 8) < N_NODES;
    int jn = lane >> 2;
    int jc = (lane & 3) * 2;

#pragma unroll 1
    for (int nc = 0; nc < 16; ++nc) {
        const float* wrow0 = W1 + (nc * 8 + jn) * IN_DIM;
#pragma unroll
        for (int g = 0; g < 2; ++g) {
            const float* wrow = wrow0 + g * 64;
            uint32_t Bh[4][2], Bl[4][2];
#pragma unroll
            for (int kc = 0; kc < 4; ++kc) {
#pragma unroll
                for (int q = 0; q < 2; ++q) {
                    float2 w = *(const float2*)&wrow[kc * 16 + (lane & 3) * 2 + q * 8];
                    unsigned hi = packbf(w.x, w.y);
                    float l0 = w.x - __uint_as_float(hi << 16);
                    float l1 = w.y - __uint_as_float(hi & 0xFFFF0000u);
                    Bh[kc][q] = hi;
                    Bl[kc][q] = packbf(l0, l1);
                }
            }
            float hh[4] = {0,0,0,0}, lh[4] = {0,0,0,0}, hl[4] = {0,0,0,0};
#pragma unroll
            for (int kc = 0; kc < 4; ++kc) {
                mma4(hh, Ahi[kc], Bh[kc][0], Bh[kc][1]);
                mma4(lh, Alo[kc], Bh[kc][0], Bh[kc][1]);
                mma4(hl, Ahi[kc], Bl[kc][0], Bl[kc][1]);
            }
            float d0 = hh[0] + lh[0] + hl[0];
            float d1 = hh[1] + lh[1] + hl[1];
            float d2 = hh[2] + lh[2] + hl[2];
            float d3 = hh[3] + lh[3] + hl[3];
            float* P = g ? g_P2 : g_P1;
            int col = nc * 8 + jc;
            if (ok0) *(float2*)&P[(size_t)m0 * NH + col] = make_float2(d0, d1);
            if (ok1) *(float2*)&P[(size_t)(m0 + 8) * NH + col] = make_float2(d2, d3);
        }
    }
}

// ---------------- fused edge kernel: warp-specialized, coalesced gather ----------------
// Producers (warps 0-7): 8 threads per edge row, lane-contiguous float4 chunks
//   (chunk c = g8 + 8*i), fully coalesced LDG.128 -> SiLU -> split bf16 -> smem.
// Consumers (warps 8-11): A = W2 in regs (hi/lo), B = hdn frags from smem, 3-pass HMMA.
__global__ void __launch_bounds__(ETHREADS, 1)
edge_kernel(const float* __restrict__ enorm, const float* __restrict__ W2,
            float* __restrict__ out) {
    extern __shared__ __align__(16) char smc[];
    int tid  = threadIdx.x;
    int wid  = tid >> 5;
    int lane = tid & 31;

    if (tid < NPROD) {
        // ======================= PRODUCER =======================
        int g8 = tid & 7;          // j chunk lane (chunks c = g8, g8+8, g8+16, g8+24)
        int eL = tid >> 3;         // 0..31
        int it = 0;
        for (int tile = blockIdx.x; tile < NTILES; tile += gridDim.x, ++it) {
            int b = it & 1;
            if (it >= 2) BAR_SYNC(3 + b);            // wait EMPTY(b)
            int eb = tile * ETILE;
#pragma unroll 1
            for (int pass = 0; pass < 4; ++pass) {
                int e  = pass * 32 + eL;
                int eg = eb + e;
                int s = g_src[eg];
                int d = g_dst[eg];
                float r = __ldg(&enorm[eg]);
                float u = r * TBL_INVH;
                int i0 = (int)u;
                if (i0 > 2047) i0 = 2047;
                if (i0 < 0)    i0 = 0;
                float fr = u - (float)i0;
                const float4* P1p = (const float4*)(g_P1 + s * NH);
                const float4* P2p = (const float4*)(g_P2 + d * NH);
                const float4* T0p = (const float4*)(g_T + i0 * NH);
                const float4* T1p = T0p + 32;
                char* hiRow = smc + b * BUF_STRIDE + e * ROWB;
                char* loRow = hiRow + BUFB;

                float4 av[4], bv[4], cv[4], tv[4];
#pragma unroll
                for (int i = 0; i < 4; ++i) {
                    int c = g8 + 8 * i;
                    av[i] = __ldcg(P1p + c);
                    bv[i] = __ldcg(P2p + c);
                    cv[i] = __ldcg(T0p + c);
                    tv[i] = __ldcg(T1p + c);
                }
#pragma unroll
                for (int i = 0; i < 4; ++i) {
                    int c = g8 + 8 * i;
                    float px = av[i].x + bv[i].x + cv[i].x + fr * (tv[i].x - cv[i].x);
                    float py = av[i].y + bv[i].y + cv[i].y + fr * (tv[i].y - cv[i].y);
                    float pz = av[i].z + bv[i].z + cv[i].z + fr * (tv[i].z - cv[i].z);
                    float pw = av[i].w + bv[i].w + cv[i].w + fr * (tv[i].w - cv[i].w);
                    float v0 = __fdividef(px, 1.0f + __expf(-px));
                    float v1 = __fdividef(py, 1.0f + __expf(-py));
                    float v2 = __fdividef(pz, 1.0f + __expf(-pz));
                    float v3 = __fdividef(pw, 1.0f + __expf(-pw));
                    unsigned p01 = packbf(v0, v1);
                    unsigned p23 = packbf(v2, v3);
                    float l0 = v0 - __uint_as_float(p01 << 16);
                    float l1 = v1 - __uint_as_float(p01 & 0xFFFF0000u);
                    float l2 = v2 - __uint_as_float(p23 << 16);
                    float l3 = v3 - __uint_as_float(p23 & 0xFFFF0000u);
                    *(uint2*)(hiRow + c * 8) = make_uint2(p01, p23);
                    *(uint2*)(loRow + c * 8) = make_uint2(packbf(l0, l1), packbf(l2, l3));
                }
            }
            __threadfence_block();
            BAR_ARRIVE(1 + b);                       // signal FULL(b)
        }
    } else {
        // ======================= CONSUMER =======================
        int mc = wid - 8;                            // 16 output cols
        uint32_t Ahi[8][4], Alo[8][4];
        {
            int r0 = mc * 16 + (lane >> 2);
            int q2 = (lane & 3) * 2;
#pragma unroll
            for (int kc = 0; kc < 8; ++kc) {
#pragma unroll
                for (int p = 0; p < 4; ++p) {
                    int r = r0 + ((p & 1) ? 8 : 0);
                    int k = kc * 16 + q2 + ((p & 2) ? 8 : 0);
                    float2 w = *(const float2*)&W2[r * NH + k];
                    unsigned hi = packbf(w.x, w.y);
                    float l0 = w.x - __uint_as_float(hi << 16);
                    float l1 = w.y - __uint_as_float(hi & 0xFFFF0000u);
                    Ahi[kc][p] = hi;
                    Alo[kc][p] = packbf(l0, l1);
                }
            }
        }
        int nb = mc * 16 + (lane >> 2);
        int it = 0;
        for (int tile = blockIdx.x; tile < NTILES; tile += gridDim.x, ++it) {
            int b = it & 1;
            BAR_SYNC(1 + b);                         // wait FULL(b)
            const char* base = smc + b * BUF_STRIDE;
            int eb = tile * ETILE;
#pragma unroll 1
            for (int ec = 0; ec < 16; ec += 2) {
                const char* r0h = base + (ec * 8 + (lane >> 2)) * ROWB + (lane & 3) * 4;
                const char* r1h = r0h + 8 * ROWB;
                const char* r0l = r0h + BUFB;
                const char* r1l = r1h + BUFB;
                float hh0[4] = {0,0,0,0}, lh0[4] = {0,0,0,0}, hl0[4] = {0,0,0,0};
                float hh1[4] = {0,0,0,0}, lh1[4] = {0,0,0,0}, hl1[4] = {0,0,0,0};
#pragma unroll
                for (int kc = 0; kc < 8; ++kc) {
                    uint32_t b0h0 = *(const uint32_t*)(r0h + kc * 32);
                    uint32_t b1h0 = *(const uint32_t*)(r0h + kc * 32 + 16);
                    uint32_t b0h1 = *(const uint32_t*)(r1h + kc * 32);
                    uint32_t b1h1 = *(const uint32_t*)(r1h + kc * 32 + 16);
                    mma4(hh0, Ahi[kc], b0h0, b1h0);
                    mma4(hh1, Ahi[kc], b0h1, b1h1);
                    mma4(lh0, Alo[kc], b0h0, b1h0);
                    mma4(lh1, Alo[kc], b0h1, b1h1);
                    uint32_t b0l0 = *(const uint32_t*)(r0l + kc * 32);
                    uint32_t b1l0 = *(const uint32_t*)(r0l + kc * 32 + 16);
                    uint32_t b0l1 = *(const uint32_t*)(r1l + kc * 32);
                    uint32_t b1l1 = *(const uint32_t*)(r1l + kc * 32 + 16);
                    mma4(hl0, Ahi[kc], b0l0, b1l0);
                    mma4(hl1, Ahi[kc], b0l1, b1l1);
                }
                int e0 = eb + ec * 8 + (lane & 3) * 2;
                float d0 = hh0[0] + lh0[0] + hl0[0];
                float d1 = hh0[1] + lh0[1] + hl0[1];
                float d2 = hh0[2] + lh0[2] + hl0[2];
                float d3 = hh0[3] + lh0[3] + hl0[3];
                __stcs(&out[(size_t)e0 * NOUT + nb], d0);
                __stcs(&out[(size_t)(e0 + 1) * NOUT + nb], d1);
                __stcs(&out[(size_t)e0 * NOUT + nb + 8], d2);
                __stcs(&out[(size_t)(e0 + 1) * NOUT + nb + 8], d3);
                int e1 = e0 + 8;
                d0 = hh1[0] + lh1[0] + hl1[0];
                d1 = hh1[1] + lh1[1] + hl1[1];
                d2 = hh1[2] + lh1[2] + hl1[2];
                d3 = hh1[3] + lh1[3] + hl1[3];
                __stcs(&out[(size_t)e1 * NOUT + nb], d0);
                __stcs(&out[(size_t)(e1 + 1) * NOUT + nb], d1);
                __stcs(&out[(size_t)e1 * NOUT + nb + 8], d2);
                __stcs(&out[(size_t)(e1 + 1) * NOUT + nb + 8], d3);
            }
            BAR_ARRIVE(3 + b);                       // signal EMPTY(b)
        }
    }
}

// ---------------- launcher ----------------
extern "C" void kernel_launch(void* const* d_in, const int* in_sizes, int n_in,
                              void* d_out, int out_size) {
    const float* h   = (const float*)d_in[0];
    const void*  src = d_in[1];
    const void*  dst = d_in[2];
    const float* en  = (const float*)d_in[3];
    const float* mu  = (const float*)d_in[4];
    const float* W1  = (const float*)d_in[5];
    const float* W2  = (const float*)d_in[6];
    float* out = (float*)d_out;

    cudaFuncSetAttribute(edge_kernel,  cudaFuncAttributeMaxDynamicSharedMemorySize, EDGE_SMEM);
    cudaFuncSetAttribute(table_kernel, cudaFuncAttributeMaxDynamicSharedMemorySize, TSMEM);

    detect_kernel<<<1, 1>>>((const unsigned int*)src);
    convert_kernel<<<(N_EDGES + 255) / 256, 256>>>(src, dst);
    table_kernel<<<(TROWS + TBLK - 1) / TBLK, 256, TSMEM>>>(mu, W1);
    node_kernel<<<(N_NODES + 127) / 128, 256>>>(h, W1);
    edge_kernel<<<148, ETHREADS, EDGE_SMEM>>>(en, W2, out);
}

// round 10
// speedup vs baseline: 2.9399x; 1.1710x over previous
#include <cuda_runtime.h>
#include <cuda_bf16.h>
#include <cstdint>

#define N_NODES 50000
#define N_EDGES 800000
#define NF 64
#define NH 128
#define NOUT 64
#define NMU 100
#define IN_DIM (2*NF + NMU)   /* 228 */

#define TROWS 2049            /* RBF lookup table rows, r in [0,10], h = 10/2048 */
#define TBL_INVH 204.8f       /* 2048/10 */

#define ETILE 64              /* edges per tile */
#define ETHREADS 256          /* 4 producer warps + 4 consumer warps */
#define NPROD 128
#define NTILES (N_EDGES / ETILE)   /* 12500 exactly */

#define APAD 136              /* padded hdn row, bf16 elems (68 words -> bank shift 4/row) */
#define ROWB (APAD * 2)       /* 272 bytes */
#define BUFB (ETILE * ROWB)   /* one bf16 matrix: 17408 B */
#define BUF_STRIDE (2 * BUFB) /* hi+lo: 34816 B */
#define EDGE_SMEM (2 * BUF_STRIDE)  /* 69632 B -> 2 CTAs/SM */

#define TBLK 16               /* table rows per block */
#define TSMEM ((NMU * NH + 128) * 4)   /* 51712 B */

/* fused prep kernel block ranges */
#define CONV_BLKS ((N_EDGES + 255) / 256)          /* 3125 */
#define TAB_BLKS  ((TROWS + TBLK - 1) / TBLK)      /* 129 */
#define NODE_BLKS ((N_NODES + 127) / 128)          /* 391 */
#define PREP_BLKS (CONV_BLKS + TAB_BLKS + NODE_BLKS)

// ---------------- device scratch (no allocations allowed) ----------------
__device__ float g_P1[N_NODES * NH];   // h @ W1[:, :64].T   per node
__device__ float g_P2[N_NODES * NH];   // h @ W1[:, 64:128].T per node
__device__ float g_T [TROWS * NH];     // RBF-contribution lookup table
__device__ int   g_src[N_EDGES];
__device__ int   g_dst[N_EDGES];
__device__ int   g_is64;

// pack two f32 -> bf16x2; low half = first arg
__device__ __forceinline__ unsigned packbf(float lo_elem, float hi_elem) {
    unsigned r;
    asm("cvt.rn.bf16x2.f32 %0, %1, %2;" : "=r"(r) : "f"(hi_elem), "f"(lo_elem));
    return r;
}

__device__ __forceinline__ void mma4(float* d, const uint32_t* a, uint32_t b0, uint32_t b1) {
    asm volatile("mma.sync.aligned.m16n8k16.row.col.f32.bf16.bf16.f32 "
                 "{%0,%1,%2,%3}, {%4,%5,%6,%7}, {%8,%9}, {%0,%1,%2,%3};"
                 : "+f"(d[0]), "+f"(d[1]), "+f"(d[2]), "+f"(d[3])
                 : "r"(a[0]), "r"(a[1]), "r"(a[2]), "r"(a[3]), "r"(b0), "r"(b1));
}

#define BAR_SYNC(id)   asm volatile("bar.sync %0, 256;"   :: "r"(id) : "memory")
#define BAR_ARRIVE(id) asm volatile("bar.arrive %0, 256;" :: "r"(id) : "memory")
/* barrier ids: FULL buffer b -> 1+b, EMPTY buffer b -> 3+b */

// ---------------- index dtype detection ----------------
__global__ void detect_kernel(const unsigned int* __restrict__ w) {
    int is64 = 1;
    for (int i = 0; i < 256; ++i) {
        if (w[2 * i + 1] != 0u) { is64 = 0; break; }
    }
    g_is64 = is64;
}

// ---------------- fused prep: convert | table | node (independent sections) ----------------
__global__ void __launch_bounds__(256)
prep_kernel(const void* __restrict__ src, const void* __restrict__ dst,
            const float* __restrict__ mu, const float* __restrict__ W1,
            const float* __restrict__ h) {
    int blk = blockIdx.x;
    int tid = threadIdx.x;

    if (blk < CONV_BLKS) {
        // ======== convert: int64/int32 indices -> int32 ========
        int i = blk * 256 + tid;
        if (i < N_EDGES) {
            if (g_is64) {
                g_src[i] = (int)((const long long*)src)[i];
                g_dst[i] = (int)((const long long*)dst)[i];
            } else {
                g_src[i] = ((const int*)src)[i];
                g_dst[i] = ((const int*)dst)[i];
            }
        }
        return;
    }
    if (blk < CONV_BLKS + TAB_BLKS) {
        // ======== RBF lookup table (smem-transposed W1c) ========
        extern __shared__ float tsm[];
        float* Ws  = tsm;             // [100][128]
        float* muS = tsm + NMU * NH;  // [100]
        for (int idx = tid; idx < NMU * NH; idx += 256) {
            int k = idx >> 7, j = idx & 127;
            Ws[k * NH + j] = W1[j * IN_DIM + 2 * NF + k];
        }
        if (tid < NMU) muS[tid] = mu[tid];
        __syncthreads();

        int ibase = (blk - CONV_BLKS) * TBLK;
#pragma unroll
        for (int q = 0; q < (TBLK * NH) / 256; ++q) {
            int o = q * 256 + tid;
            int i = ibase + (o >> 7);
            int j = o & 127;
            if (i < TROWS) {
                float r = (float)i * (10.0f / 2048.0f);
                float acc = 0.0f;
#pragma unroll 4
                for (int k = 0; k < NMU; ++k) {
                    float dm = muS[k] - r;
                    acc += __expf(-10.0f * dm * dm) * Ws[k * NH + j];
                }
                g_T[i * NH + j] = acc;
            }
        }
        return;
    }

    // ======== per-node partial GEMM via HMMA (split bf16, 3-pass) ========
    {
        int nb  = blk - CONV_BLKS - TAB_BLKS;
        int wid = tid >> 5, lane = tid & 31;
        int m0 = nb * 128 + wid * 16 + (lane >> 2);

        uint32_t Ahi[4][4], Alo[4][4];
#pragma unroll
        for (int kc = 0; kc < 4; ++kc) {
#pragma unroll
            for (int p = 0; p < 4; ++p) {
                int row = m0 + ((p & 1) ? 8 : 0);
                int k = kc * 16 + (lane & 3) * 2 + ((p & 2) ? 8 : 0);
                float2 v = (row < N_NODES) ? *(const float2*)&h[row * NF + k] : make_float2(0.f, 0.f);
                unsigned hi = packbf(v.x, v.y);
                float l0 = v.x - __uint_as_float(hi << 16);
                float l1 = v.y - __uint_as_float(hi & 0xFFFF0000u);
                Ahi[kc][p] = hi;
                Alo[kc][p] = packbf(l0, l1);
            }
        }
        bool ok0 = m0 < N_NODES;
        bool ok1 = (m0 + 8) < N_NODES;
        int jn = lane >> 2;
        int jc = (lane & 3) * 2;

#pragma unroll 1
        for (int nc = 0; nc < 16; ++nc) {
            const float* wrow0 = W1 + (nc * 8 + jn) * IN_DIM;
#pragma unroll
            for (int g = 0; g < 2; ++g) {
                const float* wrow = wrow0 + g * 64;
                uint32_t Bh[4][2], Bl[4][2];
#pragma unroll
                for (int kc = 0; kc < 4; ++kc) {
#pragma unroll
                    for (int q = 0; q < 2; ++q) {
                        float2 w = *(const float2*)&wrow[kc * 16 + (lane & 3) * 2 + q * 8];
                        unsigned hi = packbf(w.x, w.y);
                        float l0 = w.x - __uint_as_float(hi << 16);
                        float l1 = w.y - __uint_as_float(hi & 0xFFFF0000u);
                        Bh[kc][q] = hi;
                        Bl[kc][q] = packbf(l0, l1);
                    }
                }
                float hh[4] = {0,0,0,0}, lh[4] = {0,0,0,0}, hl[4] = {0,0,0,0};
#pragma unroll
                for (int kc = 0; kc < 4; ++kc) {
                    mma4(hh, Ahi[kc], Bh[kc][0], Bh[kc][1]);
                    mma4(lh, Alo[kc], Bh[kc][0], Bh[kc][1]);
                    mma4(hl, Ahi[kc], Bl[kc][0], Bl[kc][1]);
                }
                float d0 = hh[0] + lh[0] + hl[0];
                float d1 = hh[1] + lh[1] + hl[1];
                float d2 = hh[2] + lh[2] + hl[2];
                float d3 = hh[3] + lh[3] + hl[3];
                float* P = g ? g_P2 : g_P1;
                int col = nc * 8 + jc;
                if (ok0) *(float2*)&P[(size_t)m0 * NH + col] = make_float2(d0, d1);
                if (ok1) *(float2*)&P[(size_t)(m0 + 8) * NH + col] = make_float2(d2, d3);
            }
        }
    }
}

// ---------------- fused edge kernel: warp-specialized, 2 CTAs/SM ----------------
// Producers (warps 0-3): 8 threads per edge row, lane-contiguous float4 chunks,
//   fully coalesced LDG.128 -> lerp -> SiLU -> split bf16 -> smem.
// Consumers (warps 4-7): A = W2 in regs (hi/lo), B = hdn frags from smem, 3-pass HMMA.
__global__ void __launch_bounds__(ETHREADS, 2)
edge_kernel(const float* __restrict__ enorm, const float* __restrict__ W2,
            float* __restrict__ out) {
    extern __shared__ __align__(16) char smc[];
    int tid  = threadIdx.x;
    int wid  = tid >> 5;
    int lane = tid & 31;

    if (tid < NPROD) {
        // ======================= PRODUCER =======================
        int g8 = tid & 7;          // j chunk lane (chunks c = g8, g8+8, g8+16, g8+24)
        int eL = tid >> 3;         // 0..15
        int it = 0;
        for (int tile = blockIdx.x; tile < NTILES; tile += gridDim.x, ++it) {
            int b = it & 1;
            if (it >= 2) BAR_SYNC(3 + b);            // wait EMPTY(b)
            int eb = tile * ETILE;
#pragma unroll 1
            for (int pass = 0; pass < 4; ++pass) {
                int e  = pass * 16 + eL;
                int eg = eb + e;
                int s = g_src[eg];
                int d = g_dst[eg];
                float r = __ldg(&enorm[eg]);
                float u = r * TBL_INVH;
                int i0 = (int)u;
                if (i0 > 2047) i0 = 2047;
                if (i0 < 0)    i0 = 0;
                float fr = u - (float)i0;
                const float4* P1p = (const float4*)(g_P1 + s * NH);
                const float4* P2p = (const float4*)(g_P2 + d * NH);
                const float4* T0p = (const float4*)(g_T + i0 * NH);
                const float4* T1p = T0p + 32;
                char* hiRow = smc + b * BUF_STRIDE + e * ROWB;
                char* loRow = hiRow + BUFB;

                float4 av[4], bv[4], cv[4], tv[4];
#pragma unroll
                for (int i = 0; i < 4; ++i) {
                    int c = g8 + 8 * i;
                    av[i] = __ldcg(P1p + c);
                    bv[i] = __ldcg(P2p + c);
                    cv[i] = __ldcg(T0p + c);
                    tv[i] = __ldcg(T1p + c);
                }
#pragma unroll
                for (int i = 0; i < 4; ++i) {
                    int c = g8 + 8 * i;
                    float px = av[i].x + bv[i].x + cv[i].x + fr * (tv[i].x - cv[i].x);
                    float py = av[i].y + bv[i].y + cv[i].y + fr * (tv[i].y - cv[i].y);
                    float pz = av[i].z + bv[i].z + cv[i].z + fr * (tv[i].z - cv[i].z);
                    float pw = av[i].w + bv[i].w + cv[i].w + fr * (tv[i].w - cv[i].w);
                    float v0 = __fdividef(px, 1.0f + __expf(-px));
                    float v1 = __fdividef(py, 1.0f + __expf(-py));
                    float v2 = __fdividef(pz, 1.0f + __expf(-pz));
                    float v3 = __fdividef(pw, 1.0f + __expf(-pw));
                    unsigned p01 = packbf(v0, v1);
                    unsigned p23 = packbf(v2, v3);
                    float l0 = v0 - __uint_as_float(p01 << 16);
                    float l1 = v1 - __uint_as_float(p01 & 0xFFFF0000u);
                    float l2 = v2 - __uint_as_float(p23 << 16);
                    float l3 = v3 - __uint_as_float(p23 & 0xFFFF0000u);
                    *(uint2*)(hiRow + c * 8) = make_uint2(p01, p23);
                    *(uint2*)(loRow + c * 8) = make_uint2(packbf(l0, l1), packbf(l2, l3));
                }
            }
            __threadfence_block();
            BAR_ARRIVE(1 + b);                       // signal FULL(b)
        }
    } else {
        // ======================= CONSUMER =======================
        int mc = wid - 4;                            // 16 output cols
        uint32_t Ahi[8][4], Alo[8][4];
        {
            int r0 = mc * 16 + (lane >> 2);
            int q2 = (lane & 3) * 2;
#pragma unroll
            for (int kc = 0; kc < 8; ++kc) {
#pragma unroll
                for (int p = 0; p < 4; ++p) {
                    int r = r0 + ((p & 1) ? 8 : 0);
                    int k = kc * 16 + q2 + ((p & 2) ? 8 : 0);
                    float2 w = *(const float2*)&W2[r * NH + k];
                    unsigned hi = packbf(w.x, w.y);
                    float l0 = w.x - __uint_as_float(hi << 16);
                    float l1 = w.y - __uint_as_float(hi & 0xFFFF0000u);
                    Ahi[kc][p] = hi;
                    Alo[kc][p] = packbf(l0, l1);
                }
            }
        }
        int nb = mc * 16 + (lane >> 2);
        int it = 0;
        for (int tile = blockIdx.x; tile < NTILES; tile += gridDim.x, ++it) {
            int b = it & 1;
            BAR_SYNC(1 + b);                         // wait FULL(b)
            const char* base = smc + b * BUF_STRIDE;
            int eb = tile * ETILE;
#pragma unroll 1
            for (int ec = 0; ec < 8; ec += 2) {
                const char* r0h = base + (ec * 8 + (lane >> 2)) * ROWB + (lane & 3) * 4;
                const char* r1h = r0h + 8 * ROWB;
                const char* r0l = r0h + BUFB;
                const char* r1l = r1h + BUFB;
                float hh0[4] = {0,0,0,0}, lh0[4] = {0,0,0,0}, hl0[4] = {0,0,0,0};
                float hh1[4] = {0,0,0,0}, lh1[4] = {0,0,0,0}, hl1[4] = {0,0,0,0};
#pragma unroll
                for (int kc = 0; kc < 8; ++kc) {
                    uint32_t b0h0 = *(const uint32_t*)(r0h + kc * 32);
                    uint32_t b1h0 = *(const uint32_t*)(r0h + kc * 32 + 16);
                    uint32_t b0h1 = *(const uint32_t*)(r1h + kc * 32);
                    uint32_t b1h1 = *(const uint32_t*)(r1h + kc * 32 + 16);
                    mma4(hh0, Ahi[kc], b0h0, b1h0);
                    mma4(hh1, Ahi[kc], b0h1, b1h1);
                    mma4(lh0, Alo[kc], b0h0, b1h0);
                    mma4(lh1, Alo[kc], b0h1, b1h1);
                    uint32_t b0l0 = *(const uint32_t*)(r0l + kc * 32);
                    uint32_t b1l0 = *(const uint32_t*)(r0l + kc * 32 + 16);
                    uint32_t b0l1 = *(const uint32_t*)(r1l + kc * 32);
                    uint32_t b1l1 = *(const uint32_t*)(r1l + kc * 32 + 16);
                    mma4(hl0, Ahi[kc], b0l0, b1l0);
                    mma4(hl1, Ahi[kc], b0l1, b1l1);
                }
                int e0 = eb + ec * 8 + (lane & 3) * 2;
                float d0 = hh0[0] + lh0[0] + hl0[0];
                float d1 = hh0[1] + lh0[1] + hl0[1];
                float d2 = hh0[2] + lh0[2] + hl0[2];
                float d3 = hh0[3] + lh0[3] + hl0[3];
                __stcs(&out[(size_t)e0 * NOUT + nb], d0);
                __stcs(&out[(size_t)(e0 + 1) * NOUT + nb], d1);
                __stcs(&out[(size_t)e0 * NOUT + nb + 8], d2);
                __stcs(&out[(size_t)(e0 + 1) * NOUT + nb + 8], d3);
                int e1 = e0 + 8;
                d0 = hh1[0] + lh1[0] + hl1[0];
                d1 = hh1[1] + lh1[1] + hl1[1];
                d2 = hh1[2] + lh1[2] + hl1[2];
                d3 = hh1[3] + lh1[3] + hl1[3];
                __stcs(&out[(size_t)e1 * NOUT + nb], d0);
                __stcs(&out[(size_t)(e1 + 1) * NOUT + nb], d1);
                __stcs(&out[(size_t)e1 * NOUT + nb + 8], d2);
                __stcs(&out[(size_t)(e1 + 1) * NOUT + nb + 8], d3);
            }
            BAR_ARRIVE(3 + b);                       // signal EMPTY(b)
        }
    }
}

// ---------------- launcher ----------------
extern "C" void kernel_launch(void* const* d_in, const int* in_sizes, int n_in,
                              void* d_out, int out_size) {
    const float* h   = (const float*)d_in[0];
    const void*  src = d_in[1];
    const void*  dst = d_in[2];
    const float* en  = (const float*)d_in[3];
    const float* mu  = (const float*)d_in[4];
    const float* W1  = (const float*)d_in[5];
    const float* W2  = (const float*)d_in[6];
    float* out = (float*)d_out;

    cudaFuncSetAttribute(edge_kernel, cudaFuncAttributeMaxDynamicSharedMemorySize, EDGE_SMEM);
    cudaFuncSetAttribute(prep_kernel, cudaFuncAttributeMaxDynamicSharedMemorySize, TSMEM);

    detect_kernel<<<1, 1>>>((const unsigned int*)src);
    prep_kernel<<<PREP_BLKS, 256, TSMEM>>>(src, dst, mu, W1, h);
    edge_kernel<<<296, ETHREADS, EDGE_SMEM>>>(en, W2, out);
}

// round 11
// speedup vs baseline: 3.5129x; 1.1949x over previous
#include <cuda_runtime.h>
#include <cuda_bf16.h>
#include <cuda_fp16.h>
#include <cstdint>

#define N_NODES 50000
#define N_EDGES 800000
#define NF 64
#define NH 128
#define NOUT 64
#define NMU 100
#define IN_DIM (2*NF + NMU)   /* 228 */

#define TROWS 2049            /* RBF lookup table rows, r in [0,10], h = 10/2048 */
#define TBL_INVH 204.8f       /* 2048/10 */

#define ETILE 64              /* edges per tile */
#define ETHREADS 256          /* 4 producer warps + 4 consumer warps */
#define NPROD 128
#define NTILES (N_EDGES / ETILE)   /* 12500 exactly */

#define APAD 136              /* padded hdn row, bf16 elems (68 words -> bank shift 4/row) */
#define ROWB (APAD * 2)       /* 272 bytes */
#define BUFB (ETILE * ROWB)   /* one bf16 matrix: 17408 B */
#define BUF_STRIDE (2 * BUFB) /* hi+lo: 34816 B */
#define EDGE_SMEM (2 * BUF_STRIDE)  /* 69632 B -> 2 CTAs/SM */

#define TBLK 16               /* table rows per block */
#define TSMEM ((NMU * NH + 128) * 4)   /* 51712 B */

/* fused prep kernel block ranges (node first: heavy blocks start earliest) */
#define NODE_BLKS ((N_NODES + 127) / 128)          /* 391 */
#define TAB_BLKS  ((TROWS + TBLK - 1) / TBLK)      /* 129 */
#define CONV_BLKS ((N_EDGES + 255) / 256)          /* 3125 */
#define PREP_BLKS (NODE_BLKS + TAB_BLKS + CONV_BLKS)

// ---------------- device scratch (no allocations allowed) ----------------
// P1/P2/table stored as packed half2 (one uint32 = 2 fp16), rows of 64 words (256 B)
__device__ uint32_t g_P1h[N_NODES * 64];
__device__ uint32_t g_P2h[N_NODES * 64];
__device__ uint32_t g_Th [TROWS * 64];
__device__ int      g_src[N_EDGES];
__device__ int      g_dst[N_EDGES];
__device__ int      g_is64;

// pack two f32 -> bf16x2; low half = first arg
__device__ __forceinline__ unsigned packbf(float lo_elem, float hi_elem) {
    unsigned r;
    asm("cvt.rn.bf16x2.f32 %0, %1, %2;" : "=r"(r) : "f"(hi_elem), "f"(lo_elem));
    return r;
}
__device__ __forceinline__ uint32_t packh(float lo_elem, float hi_elem) {
    __half2 h = __floats2half2_rn(lo_elem, hi_elem);
    return *(uint32_t*)&h;
}
__device__ __forceinline__ float2 unpackh(uint32_t w) {
    return __half22float2(*(__half2*)&w);
}

__device__ __forceinline__ void mma4(float* d, const uint32_t* a, uint32_t b0, uint32_t b1) {
    asm volatile("mma.sync.aligned.m16n8k16.row.col.f32.bf16.bf16.f32 "
                 "{%0,%1,%2,%3}, {%4,%5,%6,%7}, {%8,%9}, {%0,%1,%2,%3};"
                 : "+f"(d[0]), "+f"(d[1]), "+f"(d[2]), "+f"(d[3])
                 : "r"(a[0]), "r"(a[1]), "r"(a[2]), "r"(a[3]), "r"(b0), "r"(b1));
}

#define BAR_SYNC(id)   asm volatile("bar.sync %0, 256;"   :: "r"(id) : "memory")
#define BAR_ARRIVE(id) asm volatile("bar.arrive %0, 256;" :: "r"(id) : "memory")
/* barrier ids: FULL buffer b -> 1+b, EMPTY buffer b -> 3+b */

// ---------------- index dtype detection (warp-parallel) ----------------
__global__ void detect_kernel(const unsigned int* __restrict__ w) {
    int lane = threadIdx.x;
    unsigned acc = 0;
#pragma unroll
    for (int i = 0; i < 8; ++i) acc |= w[2 * (lane * 8 + i) + 1];
    int any = __any_sync(0xffffffffu, acc != 0u);
    if (lane == 0) g_is64 = !any;
}

// ---------------- fused prep: node | table | convert ----------------
__global__ void __launch_bounds__(256)
prep_kernel(const void* __restrict__ src, const void* __restrict__ dst,
            const float* __restrict__ mu, const float* __restrict__ W1,
            const float* __restrict__ h) {
    int blk = blockIdx.x;
    int tid = threadIdx.x;

    if (blk < NODE_BLKS) {
        // ======== per-node partial GEMM via HMMA (split bf16, 3-pass) -> fp16 P ========
        int wid = tid >> 5, lane = tid & 31;
        int m0 = blk * 128 + wid * 16 + (lane >> 2);

        uint32_t Ahi[4][4], Alo[4][4];
#pragma unroll
        for (int kc = 0; kc < 4; ++kc) {
#pragma unroll
            for (int p = 0; p < 4; ++p) {
                int row = m0 + ((p & 1) ? 8 : 0);
                int k = kc * 16 + (lane & 3) * 2 + ((p & 2) ? 8 : 0);
                float2 v = (row < N_NODES) ? *(const float2*)&h[row * NF + k] : make_float2(0.f, 0.f);
                unsigned hi = packbf(v.x, v.y);
                float l0 = v.x - __uint_as_float(hi << 16);
                float l1 = v.y - __uint_as_float(hi & 0xFFFF0000u);
                Ahi[kc][p] = hi;
                Alo[kc][p] = packbf(l0, l1);
            }
        }
        bool ok0 = m0 < N_NODES;
        bool ok1 = (m0 + 8) < N_NODES;
        int jn = lane >> 2;

#pragma unroll 1
        for (int nc = 0; nc < 16; ++nc) {
            const float* wrow0 = W1 + (nc * 8 + jn) * IN_DIM;
#pragma unroll
            for (int g = 0; g < 2; ++g) {
                const float* wrow = wrow0 + g * 64;
                uint32_t Bh[4][2], Bl[4][2];
#pragma unroll
                for (int kc = 0; kc < 4; ++kc) {
#pragma unroll
                    for (int q = 0; q < 2; ++q) {
                        float2 w = *(const float2*)&wrow[kc * 16 + (lane & 3) * 2 + q * 8];
                        unsigned hi = packbf(w.x, w.y);
                        float l0 = w.x - __uint_as_float(hi << 16);
                        float l1 = w.y - __uint_as_float(hi & 0xFFFF0000u);
                        Bh[kc][q] = hi;
                        Bl[kc][q] = packbf(l0, l1);
                    }
                }
                float hh[4] = {0,0,0,0}, lh[4] = {0,0,0,0}, hl[4] = {0,0,0,0};
#pragma unroll
                for (int kc = 0; kc < 4; ++kc) {
                    mma4(hh, Ahi[kc], Bh[kc][0], Bh[kc][1]);
                    mma4(lh, Alo[kc], Bh[kc][0], Bh[kc][1]);
                    mma4(hl, Ahi[kc], Bl[kc][0], Bl[kc][1]);
                }
                float d0 = hh[0] + lh[0] + hl[0];
                float d1 = hh[1] + lh[1] + hl[1];
                float d2 = hh[2] + lh[2] + hl[2];
                float d3 = hh[3] + lh[3] + hl[3];
                uint32_t* P = g ? g_P2h : g_P1h;
                int wi = nc * 4 + (lane & 3);
                if (ok0) P[(size_t)m0 * 64 + wi] = packh(d0, d1);
                if (ok1) P[(size_t)(m0 + 8) * 64 + wi] = packh(d2, d3);
            }
        }
        return;
    }
    if (blk < NODE_BLKS + TAB_BLKS) {
        // ======== RBF lookup table (smem-transposed W1c) -> fp16 ========
        extern __shared__ float tsm[];
        float* Ws  = tsm;             // [100][128]
        float* muS = tsm + NMU * NH;  // [100]
        for (int idx = tid; idx < NMU * NH; idx += 256) {
            int k = idx >> 7, j = idx & 127;
            Ws[k * NH + j] = W1[j * IN_DIM + 2 * NF + k];
        }
        if (tid < NMU) muS[tid] = mu[tid];
        __syncthreads();

        int ibase = (blk - NODE_BLKS) * TBLK;
#pragma unroll
        for (int q = 0; q < (TBLK * 64) / 256; ++q) {
            int o = q * 256 + tid;
            int i = ibase + (o >> 6);
            int jw = o & 63;
            if (i < TROWS) {
                float r = (float)i * (10.0f / 2048.0f);
                float a0 = 0.0f, a1 = 0.0f;
#pragma unroll 4
                for (int k = 0; k < NMU; ++k) {
                    float dm = muS[k] - r;
                    float e = __expf(-10.0f * dm * dm);
                    float2 w = *(const float2*)&Ws[k * NH + 2 * jw];
                    a0 += e * w.x;
                    a1 += e * w.y;
                }
                g_Th[i * 64 + jw] = packh(a0, a1);
            }
        }
        return;
    }
    // ======== convert: int64/int32 indices -> int32 ========
    {
        int i = (blk - NODE_BLKS - TAB_BLKS) * 256 + tid;
        if (i < N_EDGES) {
            if (g_is64) {
                g_src[i] = (int)((const long long*)src)[i];
                g_dst[i] = (int)((const long long*)dst)[i];
            } else {
                g_src[i] = ((const int*)src)[i];
                g_dst[i] = ((const int*)dst)[i];
            }
        }
    }
}

// ---------------- fused edge kernel: warp-specialized, fp16 gather, 2 CTAs/SM ----------------
// Producers (warps 0-3): 8 threads per edge row, 2 uint4 chunks each (fp16 rows, 256 B),
//   fully coalesced -> lerp -> SiLU -> split bf16 -> smem.
// Consumers (warps 4-7): A = W2 in regs (hi/lo), B = hdn frags from smem, 3-pass HMMA.
__global__ void __launch_bounds__(ETHREADS, 2)
edge_kernel(const float* __restrict__ enorm, const float* __restrict__ W2,
            float* __restrict__ out) {
    extern __shared__ __align__(16) char smc[];
    int tid  = threadIdx.x;
    int wid  = tid >> 5;
    int lane = tid & 31;

    if (tid < NPROD) {
        // ======================= PRODUCER =======================
        int g8 = tid & 7;          // chunk lane: chunks c = g8 and g8+8 (uint4 = 8 fp16 = 8 j's)
        int eL = tid >> 3;         // 0..15
        int it = 0;
        for (int tile = blockIdx.x; tile < NTILES; tile += gridDim.x, ++it) {
            int b = it & 1;
            if (it >= 2) BAR_SYNC(3 + b);            // wait EMPTY(b)
            int eb = tile * ETILE;
#pragma unroll 1
            for (int pass = 0; pass < 4; ++pass) {
                int e  = pass * 16 + eL;
                int eg = eb + e;
                int s = g_src[eg];
                int d = g_dst[eg];
                float r = __ldg(&enorm[eg]);
                float u = r * TBL_INVH;
                int i0 = (int)u;
                if (i0 > 2047) i0 = 2047;
                if (i0 < 0)    i0 = 0;
                float fr = u - (float)i0;
                const uint4* P1p = (const uint4*)(g_P1h + (size_t)s * 64);
                const uint4* P2p = (const uint4*)(g_P2h + (size_t)d * 64);
                const uint4* T0p = (const uint4*)(g_Th  + (size_t)i0 * 64);
                const uint4* T1p = T0p + 16;
                char* hiRow = smc + b * BUF_STRIDE + e * ROWB;
                char* loRow = hiRow + BUFB;

                uint4 pa[2], pb[2], tc[2], td[2];
#pragma unroll
                for (int i = 0; i < 2; ++i) {
                    int c = g8 + 8 * i;
                    pa[i] = __ldcg(P1p + c);
                    pb[i] = __ldcg(P2p + c);
                    tc[i] = T0p[c];               // table: allow L1 caching
                    td[i] = T1p[c];
                }
#pragma unroll
                for (int i = 0; i < 2; ++i) {
                    int c = g8 + 8 * i;
                    uint4 H, L;
                    const uint32_t* aw = (const uint32_t*)&pa[i];
                    const uint32_t* bw = (const uint32_t*)&pb[i];
                    const uint32_t* cw = (const uint32_t*)&tc[i];
                    const uint32_t* tw = (const uint32_t*)&td[i];
                    uint32_t* Hw = (uint32_t*)&H;
                    uint32_t* Lw = (uint32_t*)&L;
#pragma unroll
                    for (int w = 0; w < 4; ++w) {
                        float2 af = unpackh(aw[w]);
                        float2 bf = unpackh(bw[w]);
                        float2 cf = unpackh(cw[w]);
                        float2 tf = unpackh(tw[w]);
                        float px = af.x + bf.x + cf.x + fr * (tf.x - cf.x);
                        float py = af.y + bf.y + cf.y + fr * (tf.y - cf.y);
                        float v0 = __fdividef(px, 1.0f + __expf(-px));
                        float v1 = __fdividef(py, 1.0f + __expf(-py));
                        unsigned p01 = packbf(v0, v1);
                        float l0 = v0 - __uint_as_float(p01 << 16);
                        float l1 = v1 - __uint_as_float(p01 & 0xFFFF0000u);
                        Hw[w] = p01;
                        Lw[w] = packbf(l0, l1);
                    }
                    *(uint4*)(hiRow + c * 16) = H;
                    *(uint4*)(loRow + c * 16) = L;
                }
            }
            __threadfence_block();
            BAR_ARRIVE(1 + b);                       // signal FULL(b)
        }
    } else {
        // ======================= CONSUMER =======================
        int mc = wid - 4;                            // 16 output cols
        uint32_t Ahi[8][4], Alo[8][4];
        {
            int r0 = mc * 16 + (lane >> 2);
            int q2 = (lane & 3) * 2;
#pragma unroll
            for (int kc = 0; kc < 8; ++kc) {
#pragma unroll
                for (int p = 0; p < 4; ++p) {
                    int r = r0 + ((p & 1) ? 8 : 0);
                    int k = kc * 16 + q2 + ((p & 2) ? 8 : 0);
                    float2 w = *(const float2*)&W2[r * NH + k];
                    unsigned hi = packbf(w.x, w.y);
                    float l0 = w.x - __uint_as_float(hi << 16);
                    float l1 = w.y - __uint_as_float(hi & 0xFFFF0000u);
                    Ahi[kc][p] = hi;
                    Alo[kc][p] = packbf(l0, l1);
                }
            }
        }
        int nb = mc * 16 + (lane >> 2);
        int it = 0;
        for (int tile = blockIdx.x; tile < NTILES; tile += gridDim.x, ++it) {
            int b = it & 1;
            BAR_SYNC(1 + b);                         // wait FULL(b)
            const char* base = smc + b * BUF_STRIDE;
            int eb = tile * ETILE;
#pragma unroll 1
            for (int ec = 0; ec < 8; ec += 2) {
                const char* r0h = base + (ec * 8 + (lane >> 2)) * ROWB + (lane & 3) * 4;
                const char* r1h = r0h + 8 * ROWB;
                const char* r0l = r0h + BUFB;
                const char* r1l = r1h + BUFB;
                float hh0[4] = {0,0,0,0}, lh0[4] = {0,0,0,0}, hl0[4] = {0,0,0,0};
                float hh1[4] = {0,0,0,0}, lh1[4] = {0,0,0,0}, hl1[4] = {0,0,0,0};
#pragma unroll
                for (int kc = 0; kc < 8; ++kc) {
                    uint32_t b0h0 = *(const uint32_t*)(r0h + kc * 32);
                    uint32_t b1h0 = *(const uint32_t*)(r0h + kc * 32 + 16);
                    uint32_t b0h1 = *(const uint32_t*)(r1h + kc * 32);
                    uint32_t b1h1 = *(const uint32_t*)(r1h + kc * 32 + 16);
                    mma4(hh0, Ahi[kc], b0h0, b1h0);
                    mma4(hh1, Ahi[kc], b0h1, b1h1);
                    mma4(lh0, Alo[kc], b0h0, b1h0);
                    mma4(lh1, Alo[kc], b0h1, b1h1);
                    uint32_t b0l0 = *(const uint32_t*)(r0l + kc * 32);
                    uint32_t b1l0 = *(const uint32_t*)(r0l + kc * 32 + 16);
                    uint32_t b0l1 = *(const uint32_t*)(r1l + kc * 32);
                    uint32_t b1l1 = *(const uint32_t*)(r1l + kc * 32 + 16);
                    mma4(hl0, Ahi[kc], b0l0, b1l0);
                    mma4(hl1, Ahi[kc], b0l1, b1l1);
                }
                int e0 = eb + ec * 8 + (lane & 3) * 2;
                float d0 = hh0[0] + lh0[0] + hl0[0];
                float d1 = hh0[1] + lh0[1] + hl0[1];
                float d2 = hh0[2] + lh0[2] + hl0[2];
                float d3 = hh0[3] + lh0[3] + hl0[3];
                __stcs(&out[(size_t)e0 * NOUT + nb], d0);
                __stcs(&out[(size_t)(e0 + 1) * NOUT + nb], d1);
                __stcs(&out[(size_t)e0 * NOUT + nb + 8], d2);
                __stcs(&out[(size_t)(e0 + 1) * NOUT + nb + 8], d3);
                int e1 = e0 + 8;
                d0 = hh1[0] + lh1[0] + hl1[0];
                d1 = hh1[1] + lh1[1] + hl1[1];
                d2 = hh1[2] + lh1[2] + hl1[2];
                d3 = hh1[3] + lh1[3] + hl1[3];
                __stcs(&out[(size_t)e1 * NOUT + nb], d0);
                __stcs(&out[(size_t)(e1 + 1) * NOUT + nb], d1);
                __stcs(&out[(size_t)e1 * NOUT + nb + 8], d2);
                __stcs(&out[(size_t)(e1 + 1) * NOUT + nb + 8], d3);
            }
            BAR_ARRIVE(3 + b);                       // signal EMPTY(b)
        }
    }
}

// ---------------- launcher ----------------
extern "C" void kernel_launch(void* const* d_in, const int* in_sizes, int n_in,
                              void* d_out, int out_size) {
    const float* h   = (const float*)d_in[0];
    const void*  src = d_in[1];
    const void*  dst = d_in[2];
    const float* en  = (const float*)d_in[3];
    const float* mu  = (const float*)d_in[4];
    const float* W1  = (const float*)d_in[5];
    const float* W2  = (const float*)d_in[6];
    float* out = (float*)d_out;

    cudaFuncSetAttribute(edge_kernel, cudaFuncAttributeMaxDynamicSharedMemorySize, EDGE_SMEM);
    cudaFuncSetAttribute(prep_kernel, cudaFuncAttributeMaxDynamicSharedMemorySize, TSMEM);

    detect_kernel<<<1, 32>>>((const unsigned int*)src);
    prep_kernel<<<PREP_BLKS, 256, TSMEM>>>(src, dst, mu, W1, h);
    edge_kernel<<<296, ETHREADS, EDGE_SMEM>>>(en, W2, out);
}

// round 12
// speedup vs baseline: 4.1415x; 1.1789x over previous
#include <cuda_runtime.h>
#include <cuda_bf16.h>
#include <cuda_fp16.h>
#include <cstdint>

#define N_NODES 50000
#define N_EDGES 800000
#define NF 64
#define NH 128
#define NOUT 64
#define NMU 100
#define IN_DIM (2*NF + NMU)   /* 228 */

#define TROWS 513             /* RBF lookup: 512 intervals over [0,10] + 1 */
#define TBL_INVH 51.2f        /* 512/10 */

#define ETILE 64              /* edges per tile */
#define ETHREADS 256          /* 4 producer warps + 4 consumer warps */
#define NPROD 128
#define NTILES (N_EDGES / ETILE)   /* 12500 exactly */

#define APAD 136              /* padded hdn row, fp16 elems (68 words -> bank shift 4/row) */
#define ROWB (APAD * 2)       /* 272 bytes */
#define BUFB (ETILE * ROWB)   /* one fp16 hdn matrix: 17408 B */
#define EDGE_SMEM (2 * BUFB)  /* double buffer: 34816 B -> L1D carveout ~158KB for table */

#define TBLK 16               /* table rows per block */
#define TSMEM ((NMU * NH + 128) * 4)   /* 51712 B */

/* fused prep kernel block ranges (node first: heavy blocks start earliest) */
#define NODE_BLKS ((N_NODES + 255) / 256)          /* 196, 256 nodes/block */
#define TAB_BLKS  ((TROWS + TBLK - 1) / TBLK)      /* 33 */
#define CONV_BLKS ((N_EDGES + 255) / 256)          /* 3125 */
#define PREP_BLKS (NODE_BLKS + TAB_BLKS + CONV_BLKS)

// ---------------- device scratch (no allocations allowed) ----------------
// P1/P2/table stored as packed half2 (one uint32 = 2 fp16), rows of 64 words (256 B)
__device__ uint32_t g_P1h[N_NODES * 64];
__device__ uint32_t g_P2h[N_NODES * 64];
__device__ uint32_t g_Th [TROWS * 64];
__device__ int      g_src[N_EDGES];
__device__ int      g_dst[N_EDGES];

// pack two f32 -> bf16x2; low half = first arg
__device__ __forceinline__ unsigned packbf(float lo_elem, float hi_elem) {
    unsigned r;
    asm("cvt.rn.bf16x2.f32 %0, %1, %2;" : "=r"(r) : "f"(hi_elem), "f"(lo_elem));
    return r;
}
__device__ __forceinline__ uint32_t packh(float lo_elem, float hi_elem) {
    __half2 h = __floats2half2_rn(lo_elem, hi_elem);
    return *(uint32_t*)&h;
}
__device__ __forceinline__ float2 unpackh(uint32_t w) {
    return __half22float2(*(__half2*)&w);
}

// bf16 MMA (node kernel)
__device__ __forceinline__ void mma4(float* d, const uint32_t* a, uint32_t b0, uint32_t b1) {
    asm volatile("mma.sync.aligned.m16n8k16.row.col.f32.bf16.bf16.f32 "
                 "{%0,%1,%2,%3}, {%4,%5,%6,%7}, {%8,%9}, {%0,%1,%2,%3};"
                 : "+f"(d[0]), "+f"(d[1]), "+f"(d[2]), "+f"(d[3])
                 : "r"(a[0]), "r"(a[1]), "r"(a[2]), "r"(a[3]), "r"(b0), "r"(b1));
}
// fp16 MMA (edge consumer)
__device__ __forceinline__ void mma4h(float* d, const uint32_t* a, uint32_t b0, uint32_t b1) {
    asm volatile("mma.sync.aligned.m16n8k16.row.col.f32.f16.f16.f32 "
                 "{%0,%1,%2,%3}, {%4,%5,%6,%7}, {%8,%9}, {%0,%1,%2,%3};"
                 : "+f"(d[0]), "+f"(d[1]), "+f"(d[2]), "+f"(d[3])
                 : "r"(a[0]), "r"(a[1]), "r"(a[2]), "r"(a[3]), "r"(b0), "r"(b1));
}

#define BAR_SYNC(id)   asm volatile("bar.sync %0, 256;"   :: "r"(id) : "memory")
#define BAR_ARRIVE(id) asm volatile("bar.arrive %0, 256;" :: "r"(id) : "memory")
/* barrier ids: FULL buffer b -> 1+b, EMPTY buffer b -> 3+b */

// ---------------- fused prep: node | table | convert(+inline detect) ----------------
__global__ void __launch_bounds__(256)
prep_kernel(const void* __restrict__ src, const void* __restrict__ dst,
            const float* __restrict__ mu, const float* __restrict__ W1,
            const float* __restrict__ h) {
    int blk = blockIdx.x;
    int tid = threadIdx.x;

    if (blk < NODE_BLKS) {
        // ======== per-node partial GEMM via HMMA (split bf16, 3-pass) -> fp16 P ========
        // 256 nodes per block: each warp owns two 16-node A sets (m0 and m0+128),
        // sharing B fragments (W1 loads + unpack amortized 2x).
        int wid = tid >> 5, lane = tid & 31;
        int m0 = blk * 256 + wid * 16 + (lane >> 2);

        uint32_t Ahi[2][4][4], Alo[2][4][4];
#pragma unroll
        for (int s = 0; s < 2; ++s) {
#pragma unroll
            for (int kc = 0; kc < 4; ++kc) {
#pragma unroll
                for (int p = 0; p < 4; ++p) {
                    int row = m0 + s * 128 + ((p & 1) ? 8 : 0);
                    int k = kc * 16 + (lane & 3) * 2 + ((p & 2) ? 8 : 0);
                    float2 v = (row < N_NODES) ? *(const float2*)&h[row * NF + k]
                                               : make_float2(0.f, 0.f);
                    unsigned hi = packbf(v.x, v.y);
                    float l0 = v.x - __uint_as_float(hi << 16);
                    float l1 = v.y - __uint_as_float(hi & 0xFFFF0000u);
                    Ahi[s][kc][p] = hi;
                    Alo[s][kc][p] = packbf(l0, l1);
                }
            }
        }
        int jn = lane >> 2;

#pragma unroll 1
        for (int nc = 0; nc < 16; ++nc) {
            const float* wrow0 = W1 + (nc * 8 + jn) * IN_DIM;
#pragma unroll
            for (int g = 0; g < 2; ++g) {
                const float* wrow = wrow0 + g * 64;
                uint32_t Bh[4][2], Bl[4][2];
#pragma unroll
                for (int kc = 0; kc < 4; ++kc) {
#pragma unroll
                    for (int q = 0; q < 2; ++q) {
                        float2 w = *(const float2*)&wrow[kc * 16 + (lane & 3) * 2 + q * 8];
                        unsigned hi = packbf(w.x, w.y);
                        float l0 = w.x - __uint_as_float(hi << 16);
                        float l1 = w.y - __uint_as_float(hi & 0xFFFF0000u);
                        Bh[kc][q] = hi;
                        Bl[kc][q] = packbf(l0, l1);
                    }
                }
                uint32_t* P = g ? g_P2h : g_P1h;
                int wi = nc * 4 + (lane & 3);
#pragma unroll
                for (int s = 0; s < 2; ++s) {
                    float hh[4] = {0,0,0,0}, lh[4] = {0,0,0,0}, hl[4] = {0,0,0,0};
#pragma unroll
                    for (int kc = 0; kc < 4; ++kc) {
                        mma4(hh, Ahi[s][kc], Bh[kc][0], Bh[kc][1]);
                        mma4(lh, Alo[s][kc], Bh[kc][0], Bh[kc][1]);
                        mma4(hl, Ahi[s][kc], Bl[kc][0], Bl[kc][1]);
                    }
                    float d0 = hh[0] + lh[0] + hl[0];
                    float d1 = hh[1] + lh[1] + hl[1];
                    float d2 = hh[2] + lh[2] + hl[2];
                    float d3 = hh[3] + lh[3] + hl[3];
                    int r0 = m0 + s * 128;
                    if (r0 < N_NODES)       P[(size_t)r0 * 64 + wi]       = packh(d0, d1);
                    if (r0 + 8 < N_NODES)   P[(size_t)(r0 + 8) * 64 + wi] = packh(d2, d3);
                }
            }
        }
        return;
    }
    if (blk < NODE_BLKS + TAB_BLKS) {
        // ======== RBF lookup table (smem-transposed W1c) -> fp16, 513 rows ========
        extern __shared__ float tsm[];
        float* Ws  = tsm;             // [100][128]
        float* muS = tsm + NMU * NH;  // [100]
        for (int idx = tid; idx < NMU * NH; idx += 256) {
            int k = idx >> 7, j = idx & 127;
            Ws[k * NH + j] = W1[j * IN_DIM + 2 * NF + k];
        }
        if (tid < NMU) muS[tid] = mu[tid];
        __syncthreads();

        int ibase = (blk - NODE_BLKS) * TBLK;
#pragma unroll
        for (int q = 0; q < (TBLK * 64) / 256; ++q) {
            int o = q * 256 + tid;
            int i = ibase + (o >> 6);
            int jw = o & 63;
            if (i < TROWS) {
                float r = (float)i * (10.0f / 512.0f);
                float a0 = 0.0f, a1 = 0.0f;
#pragma unroll 4
                for (int k = 0; k < NMU; ++k) {
                    float dm = muS[k] - r;
                    float e = __expf(-10.0f * dm * dm);
                    float2 w = *(const float2*)&Ws[k * NH + 2 * jw];
                    a0 += e * w.x;
                    a1 += e * w.y;
                }
                g_Th[i * 64 + jw] = packh(a0, a1);
            }
        }
        return;
    }
    // ======== convert: int64/int32 indices -> int32 (detect inlined, block-local) ========
    {
        // every block derives is64 from the same first 512 words of src -> consistent
        unsigned oddw = ((const unsigned*)src)[2 * tid + 1];
        int any = __syncthreads_or(oddw != 0u);
        int is64 = !any;
        int i = (blk - NODE_BLKS - TAB_BLKS) * 256 + tid;
        if (i < N_EDGES) {
            if (is64) {
                g_src[i] = (int)((const long long*)src)[i];
                g_dst[i] = (int)((const long long*)dst)[i];
            } else {
                g_src[i] = ((const int*)src)[i];
                g_dst[i] = ((const int*)dst)[i];
            }
        }
    }
}

// ---------------- fused edge kernel: warp-specialized, fp16 everywhere ----------------
// Producers (warps 0-3): coalesced fp16 gather (P via L2/__ldcg, table via L1),
//   lerp + SiLU -> single fp16 hdn buffer in smem.
// Consumers (warps 4-7): A = W2 split fp16 hi/lo in regs (W2 effectively exact),
//   B = fp16 hdn frags from smem, 2-pass HMMA f16 -> f32 -> out.
__global__ void __launch_bounds__(ETHREADS, 2)
edge_kernel(const float* __restrict__ enorm, const float* __restrict__ W2,
            float* __restrict__ out) {
    extern __shared__ __align__(16) char smc[];
    int tid  = threadIdx.x;
    int wid  = tid >> 5;
    int lane = tid & 31;

    if (tid < NPROD) {
        // ======================= PRODUCER =======================
        int g8 = tid & 7;          // chunk lane: chunks c = g8 and g8+8 (uint4 = 8 fp16)
        int eL = tid >> 3;         // 0..15
        int it = 0;
        for (int tile = blockIdx.x; tile < NTILES; tile += gridDim.x, ++it) {
            int b = it & 1;
            if (it >= 2) BAR_SYNC(3 + b);            // wait EMPTY(b)
            int eb = tile * ETILE;
#pragma unroll 1
            for (int pass = 0; pass < 4; ++pass) {
                int e  = pass * 16 + eL;
                int eg = eb + e;
                int s = __ldcg(&g_src[eg]);
                int d = __ldcg(&g_dst[eg]);
                float r = __ldcg(&enorm[eg]);
                float u = r * TBL_INVH;
                int i0 = (int)u;
                if (i0 > 511) i0 = 511;
                if (i0 < 0)   i0 = 0;
                float fr = u - (float)i0;
                const uint4* P1p = (const uint4*)(g_P1h + (size_t)s * 64);
                const uint4* P2p = (const uint4*)(g_P2h + (size_t)d * 64);
                const uint4* T0p = (const uint4*)(g_Th  + (size_t)i0 * 64);
                const uint4* T1p = T0p + 16;
                char* hiRow = smc + b * BUFB + e * ROWB;

                uint4 pa[2], pb[2], tc[2], td[2];
#pragma unroll
                for (int i = 0; i < 2; ++i) {
                    int c = g8 + 8 * i;
                    pa[i] = __ldcg(P1p + c);
                    pb[i] = __ldcg(P2p + c);
                    tc[i] = T0p[c];               // table: L1-resident (128 KB)
                    td[i] = T1p[c];
                }
#pragma unroll
                for (int i = 0; i < 2; ++i) {
                    int c = g8 + 8 * i;
                    uint4 H;
                    const uint32_t* aw = (const uint32_t*)&pa[i];
                    const uint32_t* bw = (const uint32_t*)&pb[i];
                    const uint32_t* cw = (const uint32_t*)&tc[i];
                    const uint32_t* tw = (const uint32_t*)&td[i];
                    uint32_t* Hw = (uint32_t*)&H;
#pragma unroll
                    for (int w = 0; w < 4; ++w) {
                        float2 af = unpackh(aw[w]);
                        float2 bf = unpackh(bw[w]);
                        float2 cf = unpackh(cw[w]);
                        float2 tf = unpackh(tw[w]);
                        float px = af.x + bf.x + cf.x + fr * (tf.x - cf.x);
                        float py = af.y + bf.y + cf.y + fr * (tf.y - cf.y);
                        float v0 = __fdividef(px, 1.0f + __expf(-px));
                        float v1 = __fdividef(py, 1.0f + __expf(-py));
                        Hw[w] = packh(v0, v1);
                    }
                    *(uint4*)(hiRow + c * 16) = H;
                }
            }
            __threadfence_block();
            BAR_ARRIVE(1 + b);                       // signal FULL(b)
        }
    } else {
        // ======================= CONSUMER =======================
        int mc = wid - 4;                            // 16 output cols
        uint32_t Ahi[8][4], Alo[8][4];               // W2 fp16 hi + residual
        {
            int r0 = mc * 16 + (lane >> 2);
            int q2 = (lane & 3) * 2;
#pragma unroll
            for (int kc = 0; kc < 8; ++kc) {
#pragma unroll
                for (int p = 0; p < 4; ++p) {
                    int r = r0 + ((p & 1) ? 8 : 0);
                    int k = kc * 16 + q2 + ((p & 2) ? 8 : 0);
                    float2 w = *(const float2*)&W2[r * NH + k];
                    uint32_t hi = packh(w.x, w.y);
                    float2 hf = unpackh(hi);
                    Ahi[kc][p] = hi;
                    Alo[kc][p] = packh(w.x - hf.x, w.y - hf.y);
                }
            }
        }
        int nb = mc * 16 + (lane >> 2);
        int it = 0;
        for (int tile = blockIdx.x; tile < NTILES; tile += gridDim.x, ++it) {
            int b = it & 1;
            BAR_SYNC(1 + b);                         // wait FULL(b)
            const char* base = smc + b * BUFB;
            int eb = tile * ETILE;
#pragma unroll 1
            for (int ec = 0; ec < 8; ec += 2) {
                const char* r0h = base + (ec * 8 + (lane >> 2)) * ROWB + (lane & 3) * 4;
                const char* r1h = r0h + 8 * ROWB;
                float hh0[4] = {0,0,0,0}, hl0[4] = {0,0,0,0};
                float hh1[4] = {0,0,0,0}, hl1[4] = {0,0,0,0};
#pragma unroll
                for (int kc = 0; kc < 8; ++kc) {
                    uint32_t b00 = *(const uint32_t*)(r0h + kc * 32);
                    uint32_t b01 = *(const uint32_t*)(r0h + kc * 32 + 16);
                    uint32_t b10 = *(const uint32_t*)(r1h + kc * 32);
                    uint32_t b11 = *(const uint32_t*)(r1h + kc * 32 + 16);
                    mma4h(hh0, Ahi[kc], b00, b01);
                    mma4h(hh1, Ahi[kc], b10, b11);
                    mma4h(hl0, Alo[kc], b00, b01);
                    mma4h(hl1, Alo[kc], b10, b11);
                }
                int e0 = eb + ec * 8 + (lane & 3) * 2;
                __stcs(&out[(size_t)e0 * NOUT + nb],           hh0[0] + hl0[0]);
                __stcs(&out[(size_t)(e0 + 1) * NOUT + nb],     hh0[1] + hl0[1]);
                __stcs(&out[(size_t)e0 * NOUT + nb + 8],       hh0[2] + hl0[2]);
                __stcs(&out[(size_t)(e0 + 1) * NOUT + nb + 8], hh0[3] + hl0[3]);
                int e1 = e0 + 8;
                __stcs(&out[(size_t)e1 * NOUT + nb],           hh1[0] + hl1[0]);
                __stcs(&out[(size_t)(e1 + 1) * NOUT + nb],     hh1[1] + hl1[1]);
                __stcs(&out[(size_t)e1 * NOUT + nb + 8],       hh1[2] + hl1[2]);
                __stcs(&out[(size_t)(e1 + 1) * NOUT + nb + 8], hh1[3] + hl1[3]);
            }
            BAR_ARRIVE(3 + b);                       // signal EMPTY(b)
        }
    }
}

// ---------------- launcher ----------------
extern "C" void kernel_launch(void* const* d_in, const int* in_sizes, int n_in,
                              void* d_out, int out_size) {
    const float* h   = (const float*)d_in[0];
    const void*  src = d_in[1];
    const void*  dst = d_in[2];
    const float* en  = (const float*)d_in[3];
    const float* mu  = (const float*)d_in[4];
    const float* W1  = (const float*)d_in[5];
    const float* W2  = (const float*)d_in[6];
    float* out = (float*)d_out;

    cudaFuncSetAttribute(edge_kernel, cudaFuncAttributeMaxDynamicSharedMemorySize, EDGE_SMEM);
    cudaFuncSetAttribute(prep_kernel, cudaFuncAttributeMaxDynamicSharedMemorySize, TSMEM);

    prep_kernel<<<PREP_BLKS, 256, TSMEM>>>(src, dst, mu, W1, h);
    edge_kernel<<<296, ETHREADS, EDGE_SMEM>>>(en, W2, out);
}